// round 2
// baseline (speedup 1.0000x reference)
#include <cuda_runtime.h>

#define EMS 1024
#define NH 16
#define HD 64
#define SEQ 2048
#define BATCH 2

// Scratch in head layout [b, h, s, d] (b*h major). Static device arrays (no alloc).
__device__ float g_Q[BATCH * NH * SEQ * HD];
__device__ float g_K[BATCH * NH * SEQ * HD];
__device__ float g_V[BATCH * NH * SEQ * HD];

// ---------------------------------------------------------------------------
// Projection: C[m,n] = A[m,:] . W[n,:] + bias[n]  (torch Linear, W is [N,K])
// M=4096, N=1024, K=1024. Tile 64x64x16, 256 threads, 4x4 per thread.
// blockIdx.z: 0 -> Q(q,Wq,bq), 1 -> K(embed,Wk,bk), 2 -> V(embed,Wv,bv)
// ---------------------------------------------------------------------------
__global__ __launch_bounds__(256) void proj_kernel(
    const float* __restrict__ embed, const float* __restrict__ qin,
    const float* __restrict__ Wq, const float* __restrict__ bq,
    const float* __restrict__ Wk, const float* __restrict__ bk,
    const float* __restrict__ Wv, const float* __restrict__ bv)
{
    __shared__ float As[16][68];   // [k][m]
    __shared__ float Ws[16][68];   // [k][n]

    const float* A; const float* W; const float* bias; float* out;
    if (blockIdx.z == 0)      { A = qin;   W = Wq; bias = bq; out = g_Q; }
    else if (blockIdx.z == 1) { A = embed; W = Wk; bias = bk; out = g_K; }
    else                      { A = embed; W = Wv; bias = bv; out = g_V; }

    const int tid = threadIdx.x;
    const int tx = tid & 15;
    const int ty = tid >> 4;
    const int m0 = blockIdx.y * 64;
    const int n0 = blockIdx.x * 64;

    const int lr = tid >> 2;           // row within tile (0..63)
    const int lk = (tid & 3) * 4;      // k offset (0,4,8,12)
    const float* Ap = A + (size_t)(m0 + lr) * EMS + lk;
    const float* Wp = W + (size_t)(n0 + lr) * EMS + lk;

    float c[4][4] = {};

    for (int k0 = 0; k0 < EMS; k0 += 16) {
        float4 av = *(const float4*)(Ap + k0);
        float4 wv = *(const float4*)(Wp + k0);
        __syncthreads();
        As[lk + 0][lr] = av.x; As[lk + 1][lr] = av.y;
        As[lk + 2][lr] = av.z; As[lk + 3][lr] = av.w;
        Ws[lk + 0][lr] = wv.x; Ws[lk + 1][lr] = wv.y;
        Ws[lk + 2][lr] = wv.z; Ws[lk + 3][lr] = wv.w;
        __syncthreads();

        #pragma unroll
        for (int kk = 0; kk < 16; kk++) {
            float4 a4 = *(const float4*)&As[kk][ty * 4];
            float4 b4 = *(const float4*)&Ws[kk][tx * 4];
            float av2[4] = {a4.x, a4.y, a4.z, a4.w};
            float bv2[4] = {b4.x, b4.y, b4.z, b4.w};
            #pragma unroll
            for (int i = 0; i < 4; i++)
                #pragma unroll
                for (int j = 0; j < 4; j++)
                    c[i][j] += av2[i] * bv2[j];
        }
    }

    #pragma unroll
    for (int i = 0; i < 4; i++) {
        const int m = m0 + ty * 4 + i;
        const int bb = m >> 11;
        const int s  = m & (SEQ - 1);
        #pragma unroll
        for (int j = 0; j < 4; j++) {
            const int n = n0 + tx * 4 + j;
            const int h  = n >> 6;
            const int dd = n & (HD - 1);
            out[(((size_t)(bb * NH + h) * SEQ) + s) * HD + dd] = c[i][j] + bias[n];
        }
    }
}

// ---------------------------------------------------------------------------
// Flash attention: per (b,h), 64-query tile per block, 64-key tiles, online
// softmax. 256 threads, 4x4 register micro-tiles for S = Q K^T and O += P V.
// Tile loaders: each thread loads FOUR float4s (64x64 = 4096 floats / 256 thr).
// ---------------------------------------------------------------------------
__global__ __launch_bounds__(256) void attn_kernel(float* __restrict__ out)
{
    extern __shared__ float sh[];
    float (*Qs)[68] = (float(*)[68])(sh);              // [d][q]  (transposed)
    float (*Ks)[68] = (float(*)[68])(sh + 64 * 68);    // [d][k]  (transposed)
    float (*Vs)[68] = (float(*)[68])(sh + 2 * 64 * 68);// [k][d]  (natural)
    float (*Ps)[68] = (float(*)[68])(sh + 3 * 64 * 68);// [k][q]  (transposed P)

    const int tid = threadIdx.x;
    const int tx = tid & 15;
    const int ty = tid >> 4;
    const int bh = blockIdx.y;           // 0..31
    const int q0 = blockIdx.x * 64;

    const float* Qb = g_Q + (size_t)bh * SEQ * HD;
    const float* Kb = g_K + (size_t)bh * SEQ * HD;
    const float* Vb = g_V + (size_t)bh * SEQ * HD;

    const int lr = tid >> 2;           // row within tile (0..63)
    const int lkb = (tid & 3) * 4;     // base column offset (0,4,8,12)

    // Load full Q tile (64 rows x 64 dims), pre-scaled by 1/sqrt(64)
    {
        const float sc = 0.125f;
        #pragma unroll
        for (int c = 0; c < 4; c++) {
            const int lk = lkb + c * 16;
            float4 qv = *(const float4*)(Qb + (size_t)(q0 + lr) * HD + lk);
            Qs[lk + 0][lr] = qv.x * sc; Qs[lk + 1][lr] = qv.y * sc;
            Qs[lk + 2][lr] = qv.z * sc; Qs[lk + 3][lr] = qv.w * sc;
        }
    }

    float m_i[4], l_i[4], o[4][4];
    #pragma unroll
    for (int i = 0; i < 4; i++) {
        m_i[i] = -1e30f; l_i[i] = 0.f;
        #pragma unroll
        for (int j = 0; j < 4; j++) o[i][j] = 0.f;
    }

    for (int k0 = 0; k0 < SEQ; k0 += 64) {
        float4 kv[4], vv[4];
        #pragma unroll
        for (int c = 0; c < 4; c++) {
            const int lk = lkb + c * 16;
            kv[c] = *(const float4*)(Kb + (size_t)(k0 + lr) * HD + lk);
            vv[c] = *(const float4*)(Vb + (size_t)(k0 + lr) * HD + lk);
        }
        __syncthreads();   // previous tile's reads of Ks/Vs/Ps done
        #pragma unroll
        for (int c = 0; c < 4; c++) {
            const int lk = lkb + c * 16;
            Ks[lk + 0][lr] = kv[c].x; Ks[lk + 1][lr] = kv[c].y;
            Ks[lk + 2][lr] = kv[c].z; Ks[lk + 3][lr] = kv[c].w;
            *(float4*)&Vs[lr][lk] = vv[c];
        }
        __syncthreads();

        // S = Q K^T
        float s[4][4] = {};
        #pragma unroll 16
        for (int dd = 0; dd < 64; dd++) {
            float4 a4 = *(const float4*)&Qs[dd][ty * 4];
            float4 b4 = *(const float4*)&Ks[dd][tx * 4];
            float av2[4] = {a4.x, a4.y, a4.z, a4.w};
            float bv2[4] = {b4.x, b4.y, b4.z, b4.w};
            #pragma unroll
            for (int i = 0; i < 4; i++)
                #pragma unroll
                for (int j = 0; j < 4; j++)
                    s[i][j] += av2[i] * bv2[j];
        }

        // Online softmax per q row (16-lane aligned groups -> width-16 shuffles)
        #pragma unroll
        for (int i = 0; i < 4; i++) {
            float mx = fmaxf(fmaxf(s[i][0], s[i][1]), fmaxf(s[i][2], s[i][3]));
            #pragma unroll
            for (int off = 8; off >= 1; off >>= 1)
                mx = fmaxf(mx, __shfl_xor_sync(0xffffffffu, mx, off, 16));
            const float mnew = fmaxf(m_i[i], mx);
            const float alpha = __expf(m_i[i] - mnew);
            m_i[i] = mnew;
            float p[4], rs = 0.f;
            #pragma unroll
            for (int j = 0; j < 4; j++) { p[j] = __expf(s[i][j] - mnew); rs += p[j]; }
            #pragma unroll
            for (int off = 8; off >= 1; off >>= 1)
                rs += __shfl_xor_sync(0xffffffffu, rs, off, 16);
            l_i[i] = l_i[i] * alpha + rs;
            #pragma unroll
            for (int j = 0; j < 4; j++) {
                o[i][j] *= alpha;
                Ps[tx * 4 + j][ty * 4 + i] = p[j];   // P transposed: [k][q]
            }
        }
        __syncthreads();

        // O += P V
        #pragma unroll 16
        for (int kk = 0; kk < 64; kk++) {
            float4 a4 = *(const float4*)&Ps[kk][ty * 4];
            float4 b4 = *(const float4*)&Vs[kk][tx * 4];
            float av2[4] = {a4.x, a4.y, a4.z, a4.w};
            float bv2[4] = {b4.x, b4.y, b4.z, b4.w};
            #pragma unroll
            for (int i = 0; i < 4; i++)
                #pragma unroll
                for (int j = 0; j < 4; j++)
                    o[i][j] += av2[i] * bv2[j];
        }
    }

    // Normalize and write out [b, sq, h*d]
    const int bb = bh >> 4;
    const int h  = bh & 15;
    #pragma unroll
    for (int i = 0; i < 4; i++) {
        const int qrow = q0 + ty * 4 + i;
        const float inv = 1.f / l_i[i];
        #pragma unroll
        for (int j = 0; j < 4; j++) {
            out[((size_t)(bb * SEQ + qrow)) * EMS + h * HD + tx * 4 + j] = o[i][j] * inv;
        }
    }
}

// ---------------------------------------------------------------------------
extern "C" void kernel_launch(void* const* d_in, const int* in_sizes, int n_in,
                              void* d_out, int out_size)
{
    const float* embed = (const float*)d_in[0];
    const float* q     = (const float*)d_in[1];
    const float* Wk    = (const float*)d_in[2];
    const float* bk    = (const float*)d_in[3];
    const float* Wq    = (const float*)d_in[4];
    const float* bq    = (const float*)d_in[5];
    const float* Wv    = (const float*)d_in[6];
    const float* bv    = (const float*)d_in[7];
    float* out = (float*)d_out;

    dim3 gp(EMS / 64, (BATCH * SEQ) / 64, 3);
    proj_kernel<<<gp, 256>>>(embed, q, Wq, bq, Wk, bk, Wv, bv);

    const int smem_attn = 4 * 64 * 68 * (int)sizeof(float);  // 69632 B
    cudaFuncSetAttribute(attn_kernel, cudaFuncAttributeMaxDynamicSharedMemorySize, smem_attn);
    attn_kernel<<<dim3(SEQ / 64, BATCH * NH), 256, smem_attn>>>(out);
}

// round 4
// speedup vs baseline: 1.3863x; 1.3863x over previous
#include <cuda_runtime.h>
#include <cuda_bf16.h>
#include <cstdint>

#define EMS 1024
#define NH 16
#define HD 64
#define SEQ 2048
#define BATCH 2

// ---------------------------------------------------------------------------
// PTX helpers (non-'a' features only: ldmatrix, mma.sync, cp.async, f32x2)
// ---------------------------------------------------------------------------
__device__ __forceinline__ uint32_t smem_u32(const void* p) {
    uint32_t a;
    asm("{ .reg .u64 t; cvta.to.shared.u64 t, %1; cvt.u32.u64 %0, t; }" : "=r"(a) : "l"(p));
    return a;
}
#define CP_ASYNC16(dst, src) \
    asm volatile("cp.async.cg.shared.global [%0], [%1], 16;" :: "r"(dst), "l"(src) : "memory")
#define CP_COMMIT() asm volatile("cp.async.commit_group;" ::: "memory")
#define CP_WAIT(n)  asm volatile("cp.async.wait_group %0;" :: "n"(n) : "memory")

__device__ __forceinline__ void ldsm_x4(uint32_t* r, uint32_t addr) {
    asm volatile("ldmatrix.sync.aligned.m8n8.x4.shared.b16 {%0,%1,%2,%3}, [%4];"
        : "=r"(r[0]), "=r"(r[1]), "=r"(r[2]), "=r"(r[3]) : "r"(addr));
}
__device__ __forceinline__ void mma16816(float* c, const uint32_t* a, const uint32_t* b) {
    asm volatile("mma.sync.aligned.m16n8k16.row.col.f32.bf16.bf16.f32 "
        "{%0,%1,%2,%3}, {%4,%5,%6,%7}, {%8,%9}, {%0,%1,%2,%3};"
        : "+f"(c[0]), "+f"(c[1]), "+f"(c[2]), "+f"(c[3])
        : "r"(a[0]), "r"(a[1]), "r"(a[2]), "r"(a[3]), "r"(b[0]), "r"(b[1]));
}

// f32x2 packed math
__device__ __forceinline__ unsigned long long pk2(float a, float b) {
    unsigned long long r; asm("mov.b64 %0, {%1, %2};" : "=l"(r) : "f"(a), "f"(b)); return r;
}
__device__ __forceinline__ void ffma2(unsigned long long& d, unsigned long long a, unsigned long long b) {
    asm("fma.rn.f32x2 %0, %1, %2, %0;" : "+l"(d) : "l"(a), "l"(b));
}
__device__ __forceinline__ void fmul2(unsigned long long& d, unsigned long long a) {
    asm("mul.rn.f32x2 %0, %0, %1;" : "+l"(d) : "l"(a));
}
__device__ __forceinline__ float2 up2(unsigned long long v) {
    float2 f; asm("mov.b64 {%0, %1}, %2;" : "=f"(f.x), "=f"(f.y) : "l"(v)); return f;
}

// ---------------------------------------------------------------------------
// Device scratch
// ---------------------------------------------------------------------------
__device__ float g_Q[BATCH * NH * SEQ * HD];
__device__ float g_K[BATCH * NH * SEQ * HD];
__device__ float g_V[BATCH * NH * SEQ * HD];
__device__ __nv_bfloat16 g_Eh[4096 * 1024], g_El[4096 * 1024];
__device__ __nv_bfloat16 g_Xh[4096 * 1024], g_Xl[4096 * 1024];
__device__ __nv_bfloat16 g_Wqh[1024 * 1024], g_Wql[1024 * 1024];
__device__ __nv_bfloat16 g_Wkh[1024 * 1024], g_Wkl[1024 * 1024];
__device__ __nv_bfloat16 g_Wvh[1024 * 1024], g_Wvl[1024 * 1024];

// ---------------------------------------------------------------------------
// fp32 -> bf16 hi/lo split
// ---------------------------------------------------------------------------
__global__ __launch_bounds__(256) void convert_kernel(
    const float* __restrict__ embed, const float* __restrict__ qin,
    const float* __restrict__ Wq, const float* __restrict__ Wk, const float* __restrict__ Wv)
{
    const int z = blockIdx.y;
    const float* src; __nv_bfloat16* hi; __nv_bfloat16* lo; int n4;
    switch (z) {
        case 0: src = embed; hi = g_Eh;  lo = g_El;  n4 = 4096 * 256; break;
        case 1: src = qin;   hi = g_Xh;  lo = g_Xl;  n4 = 4096 * 256; break;
        case 2: src = Wq;    hi = g_Wqh; lo = g_Wql; n4 = 1024 * 256; break;
        case 3: src = Wk;    hi = g_Wkh; lo = g_Wkl; n4 = 1024 * 256; break;
        default: src = Wv;   hi = g_Wvh; lo = g_Wvl; n4 = 1024 * 256; break;
    }
    const int t = blockIdx.x * 256 + threadIdx.x;
    if (t >= n4) return;
    float4 v = ((const float4*)src)[t];
    __nv_bfloat16 h0 = __float2bfloat16(v.x), h1 = __float2bfloat16(v.y);
    __nv_bfloat16 h2 = __float2bfloat16(v.z), h3 = __float2bfloat16(v.w);
    __nv_bfloat16 l0 = __float2bfloat16(v.x - __bfloat162float(h0));
    __nv_bfloat16 l1 = __float2bfloat16(v.y - __bfloat162float(h1));
    __nv_bfloat16 l2 = __float2bfloat16(v.z - __bfloat162float(h2));
    __nv_bfloat16 l3 = __float2bfloat16(v.w - __bfloat162float(h3));
    __nv_bfloat162* hp = (__nv_bfloat162*)(hi + (size_t)t * 4);
    __nv_bfloat162* lp = (__nv_bfloat162*)(lo + (size_t)t * 4);
    hp[0] = __halves2bfloat162(h0, h1); hp[1] = __halves2bfloat162(h2, h3);
    lp[0] = __halves2bfloat162(l0, l1); lp[1] = __halves2bfloat162(l2, l3);
}

// ---------------------------------------------------------------------------
// mma.sync bf16 projection: C[4096,1024] = A @ W^T + bias, 3-term hi/lo split.
// 128x128 CTA tile, 8 warps as 4(M)x2(N), each warp 32x64.
// K chunks of 64, cp.async double-buffered smem, rows padded to 144B.
// ---------------------------------------------------------------------------
#define TILE_B 18432            // 128 rows * 144 B
#define BUF_B  (4 * TILE_B)     // Ah, Al, Wh, Wl

__global__ __launch_bounds__(256) void proj_mma_kernel(
    const float* __restrict__ bq, const float* __restrict__ bk, const float* __restrict__ bv)
{
    extern __shared__ char ds[];            // 2 * BUF_B = 147456
    __shared__ float s_bias[128];

    const int tid  = threadIdx.x;
    const int wid  = tid >> 5;
    const int lane = tid & 31;
    const int z  = blockIdx.z;
    const int n0 = blockIdx.x * 128;
    const int m0 = blockIdx.y * 128;

    const __nv_bfloat16 *Ah, *Al, *Bh, *Bl; const float* bias; float* outp;
    if (z == 0)      { Ah = g_Xh; Al = g_Xl; Bh = g_Wqh; Bl = g_Wql; bias = bq; outp = g_Q; }
    else if (z == 1) { Ah = g_Eh; Al = g_El; Bh = g_Wkh; Bl = g_Wkl; bias = bk; outp = g_K; }
    else             { Ah = g_Eh; Al = g_El; Bh = g_Wvh; Bl = g_Wvl; bias = bv; outp = g_V; }

    if (tid < 128) s_bias[tid] = bias[n0 + tid];

    const uint32_t smb = smem_u32(ds);
    const __nv_bfloat16* srcs[4] = {
        Ah + (size_t)m0 * 1024, Al + (size_t)m0 * 1024,
        Bh + (size_t)n0 * 1024, Bl + (size_t)n0 * 1024 };

    const int cprow = tid >> 3;          // 0..31  (row step 32 per iter)
    const int cpseg = (tid & 7) * 16;    // byte seg within 128B of payload

    // issue cp.async for chunk c into buffer c&1
    auto issue = [&](int c) {
        const uint32_t bbase = smb + (c & 1) * BUF_B;
        const int k0 = c * 64;
        #pragma unroll
        for (int t4 = 0; t4 < 4; t4++) {
            const __nv_bfloat16* sp = srcs[t4] + k0;
            const uint32_t tbase = bbase + t4 * TILE_B;
            #pragma unroll
            for (int it = 0; it < 4; it++) {
                const int r = cprow + it * 32;
                CP_ASYNC16(tbase + r * 144 + cpseg,
                           (const void*)((const char*)(sp + (size_t)r * 1024) + cpseg));
            }
        }
        CP_COMMIT();
    };

    const int wm = (wid >> 1) * 32;
    const int wn = (wid & 1) * 64;

    float acc[2][8][4];
    #pragma unroll
    for (int mt = 0; mt < 2; mt++)
        #pragma unroll
        for (int nt = 0; nt < 8; nt++)
            #pragma unroll
            for (int e = 0; e < 4; e++) acc[mt][nt][e] = 0.f;

    // ldmatrix lane addressing (bytes)
    const int a_row = lane & 15;
    const int a_kb  = ((lane >> 4) << 3) * 2;            // +8 cols for lanes>=16
    const int b_row = lane & 7;
    const int b_kb  = (((lane >> 3) & 1) << 3) * 2;      // +8 cols for bit3
    const int b_nx  = (lane >= 16) ? 8 : 0;              // second n8 of the pair

    issue(0);

    for (int c = 0; c < 16; c++) {
        if (c + 1 < 16) { issue(c + 1); CP_WAIT(1); }
        else            { CP_WAIT(0); }
        __syncthreads();

        const uint32_t bbase = smb + (c & 1) * BUF_B;
        const uint32_t Abase = bbase;
        const uint32_t Wbase = bbase + 2 * TILE_B;

        #pragma unroll
        for (int ks = 0; ks < 4; ks++) {
            const int kb = ks * 32;   // bytes: ks*16 bf16
            uint32_t aF[2][2][4];
            #pragma unroll
            for (int src = 0; src < 2; src++)
                #pragma unroll
                for (int mt = 0; mt < 2; mt++)
                    ldsm_x4(aF[src][mt],
                            Abase + src * TILE_B + (wm + mt * 16 + a_row) * 144 + kb + a_kb);

            uint32_t bF[2][8][2];
            #pragma unroll
            for (int src = 0; src < 2; src++)
                #pragma unroll
                for (int p = 0; p < 4; p++) {
                    uint32_t r4[4];
                    ldsm_x4(r4, Wbase + src * TILE_B +
                                (wn + p * 16 + b_nx + b_row) * 144 + kb + b_kb);
                    bF[src][2 * p][0] = r4[0]; bF[src][2 * p][1] = r4[1];
                    bF[src][2 * p + 1][0] = r4[2]; bF[src][2 * p + 1][1] = r4[3];
                }

            #pragma unroll
            for (int mt = 0; mt < 2; mt++)
                #pragma unroll
                for (int nt = 0; nt < 8; nt++) {
                    mma16816(acc[mt][nt], aF[0][mt], bF[0][nt]);   // hi*hi
                    mma16816(acc[mt][nt], aF[0][mt], bF[1][nt]);   // hi*lo
                    mma16816(acc[mt][nt], aF[1][mt], bF[0][nt]);   // lo*hi
                }
        }
        __syncthreads();
    }

    // Epilogue: write fragments directly to [b,h,s,d] layout with bias.
    const int rq = lane >> 2;
    const int cq = (lane & 3) * 2;
    #pragma unroll
    for (int mt = 0; mt < 2; mt++) {
        #pragma unroll
        for (int half = 0; half < 2; half++) {
            const int m  = m0 + wm + mt * 16 + rq + half * 8;
            const int bb = m >> 11;
            const int s  = m & (SEQ - 1);
            #pragma unroll
            for (int nt = 0; nt < 8; nt++) {
                const int nl = wn + nt * 8 + cq;      // 0..127 within tile
                const int n  = n0 + nl;
                const int h  = n >> 6, dd = n & 63;
                float2 v;
                v.x = acc[mt][nt][half * 2 + 0] + s_bias[nl];
                v.y = acc[mt][nt][half * 2 + 1] + s_bias[nl + 1];
                *(float2*)&outp[(((size_t)(bb * NH + h) * SEQ) + s) * HD + dd] = v;
            }
        }
    }
}

// ---------------------------------------------------------------------------
// Flash attention (f32x2 packed inner loops)
// ---------------------------------------------------------------------------
__global__ __launch_bounds__(256) void attn_kernel(float* __restrict__ out)
{
    extern __shared__ float sh[];
    float (*Qs)[68] = (float(*)[68])(sh);
    float (*Ks)[68] = (float(*)[68])(sh + 64 * 68);
    float (*Vs)[68] = (float(*)[68])(sh + 2 * 64 * 68);
    float (*Ps)[68] = (float(*)[68])(sh + 3 * 64 * 68);

    const int tid = threadIdx.x;
    const int tx = tid & 15;
    const int ty = tid >> 4;
    const int bh = blockIdx.y;
    const int q0 = blockIdx.x * 64;

    const float* Qb = g_Q + (size_t)bh * SEQ * HD;
    const float* Kb = g_K + (size_t)bh * SEQ * HD;
    const float* Vb = g_V + (size_t)bh * SEQ * HD;

    const int lr = tid >> 2;
    const int lkb = (tid & 3) * 4;

    {
        const float sc = 0.125f;
        #pragma unroll
        for (int c = 0; c < 4; c++) {
            const int lk = lkb + c * 16;
            float4 qv = *(const float4*)(Qb + (size_t)(q0 + lr) * HD + lk);
            Qs[lk + 0][lr] = qv.x * sc; Qs[lk + 1][lr] = qv.y * sc;
            Qs[lk + 2][lr] = qv.z * sc; Qs[lk + 3][lr] = qv.w * sc;
        }
    }

    float m_i[4], l_i[4];
    unsigned long long o2[4][2];
    #pragma unroll
    for (int i = 0; i < 4; i++) { m_i[i] = -1e30f; l_i[i] = 0.f; o2[i][0] = 0ull; o2[i][1] = 0ull; }

    for (int k0 = 0; k0 < SEQ; k0 += 64) {
        float4 kv[4], vv[4];
        #pragma unroll
        for (int c = 0; c < 4; c++) {
            const int lk = lkb + c * 16;
            kv[c] = *(const float4*)(Kb + (size_t)(k0 + lr) * HD + lk);
            vv[c] = *(const float4*)(Vb + (size_t)(k0 + lr) * HD + lk);
        }
        __syncthreads();
        #pragma unroll
        for (int c = 0; c < 4; c++) {
            const int lk = lkb + c * 16;
            Ks[lk + 0][lr] = kv[c].x; Ks[lk + 1][lr] = kv[c].y;
            Ks[lk + 2][lr] = kv[c].z; Ks[lk + 3][lr] = kv[c].w;
            *(float4*)&Vs[lr][lk] = vv[c];
        }
        __syncthreads();

        unsigned long long s2[4][2] = {{0ull,0ull},{0ull,0ull},{0ull,0ull},{0ull,0ull}};
        #pragma unroll 8
        for (int dd = 0; dd < 64; dd++) {
            float4 a4 = *(const float4*)&Qs[dd][ty * 4];
            ulonglong2 b2 = *(const ulonglong2*)&Ks[dd][tx * 4];
            unsigned long long A;
            A = pk2(a4.x, a4.x); ffma2(s2[0][0], A, b2.x); ffma2(s2[0][1], A, b2.y);
            A = pk2(a4.y, a4.y); ffma2(s2[1][0], A, b2.x); ffma2(s2[1][1], A, b2.y);
            A = pk2(a4.z, a4.z); ffma2(s2[2][0], A, b2.x); ffma2(s2[2][1], A, b2.y);
            A = pk2(a4.w, a4.w); ffma2(s2[3][0], A, b2.x); ffma2(s2[3][1], A, b2.y);
        }

        #pragma unroll
        for (int i = 0; i < 4; i++) {
            float2 s01 = up2(s2[i][0]);
            float2 s23 = up2(s2[i][1]);
            float s0 = s01.x, s1 = s01.y, s2v = s23.x, s3 = s23.y;
            float mx = fmaxf(fmaxf(s0, s1), fmaxf(s2v, s3));
            #pragma unroll
            for (int off = 8; off >= 1; off >>= 1)
                mx = fmaxf(mx, __shfl_xor_sync(0xffffffffu, mx, off, 16));
            const float mnew = fmaxf(m_i[i], mx);
            const float alpha = __expf(m_i[i] - mnew);
            m_i[i] = mnew;
            float p0 = __expf(s0 - mnew), p1 = __expf(s1 - mnew);
            float p2 = __expf(s2v - mnew), p3 = __expf(s3 - mnew);
            float rs = p0 + p1 + p2 + p3;
            #pragma unroll
            for (int off = 8; off >= 1; off >>= 1)
                rs += __shfl_xor_sync(0xffffffffu, rs, off, 16);
            l_i[i] = l_i[i] * alpha + rs;
            unsigned long long AL = pk2(alpha, alpha);
            fmul2(o2[i][0], AL); fmul2(o2[i][1], AL);
            Ps[tx * 4 + 0][ty * 4 + i] = p0;
            Ps[tx * 4 + 1][ty * 4 + i] = p1;
            Ps[tx * 4 + 2][ty * 4 + i] = p2;
            Ps[tx * 4 + 3][ty * 4 + i] = p3;
        }
        __syncthreads();

        #pragma unroll 8
        for (int kk = 0; kk < 64; kk++) {
            float4 p4 = *(const float4*)&Ps[kk][ty * 4];
            ulonglong2 v2 = *(const ulonglong2*)&Vs[kk][tx * 4];
            unsigned long long A;
            A = pk2(p4.x, p4.x); ffma2(o2[0][0], A, v2.x); ffma2(o2[0][1], A, v2.y);
            A = pk2(p4.y, p4.y); ffma2(o2[1][0], A, v2.x); ffma2(o2[1][1], A, v2.y);
            A = pk2(p4.z, p4.z); ffma2(o2[2][0], A, v2.x); ffma2(o2[2][1], A, v2.y);
            A = pk2(p4.w, p4.w); ffma2(o2[3][0], A, v2.x); ffma2(o2[3][1], A, v2.y);
        }
    }

    const int bb = bh >> 4;
    const int h  = bh & 15;
    #pragma unroll
    for (int i = 0; i < 4; i++) {
        const int qrow = q0 + ty * 4 + i;
        const float inv = 1.f / l_i[i];
        float2 a = up2(o2[i][0]);
        float2 b = up2(o2[i][1]);
        float4 v = make_float4(a.x * inv, a.y * inv, b.x * inv, b.y * inv);
        *(float4*)&out[((size_t)(bb * SEQ + qrow)) * EMS + h * HD + tx * 4] = v;
    }
}

// ---------------------------------------------------------------------------
extern "C" void kernel_launch(void* const* d_in, const int* in_sizes, int n_in,
                              void* d_out, int out_size)
{
    const float* embed = (const float*)d_in[0];
    const float* q     = (const float*)d_in[1];
    const float* Wk    = (const float*)d_in[2];
    const float* bk    = (const float*)d_in[3];
    const float* Wq    = (const float*)d_in[4];
    const float* bq    = (const float*)d_in[5];
    const float* Wv    = (const float*)d_in[6];
    const float* bv    = (const float*)d_in[7];
    float* out = (float*)d_out;

    convert_kernel<<<dim3(4096, 5), 256>>>(embed, q, Wq, Wk, Wv);

    cudaFuncSetAttribute(proj_mma_kernel, cudaFuncAttributeMaxDynamicSharedMemorySize, 2 * BUF_B);
    proj_mma_kernel<<<dim3(EMS / 128, (BATCH * SEQ) / 128, 3), 256, 2 * BUF_B>>>(bq, bk, bv);

    const int smem_attn = 4 * 64 * 68 * (int)sizeof(float);
    cudaFuncSetAttribute(attn_kernel, cudaFuncAttributeMaxDynamicSharedMemorySize, smem_attn);
    attn_kernel<<<dim3(SEQ / 64, BATCH * NH), 256, smem_attn>>>(out);
}

// round 5
// speedup vs baseline: 2.8749x; 2.0738x over previous
#include <cuda_runtime.h>
#include <cuda_bf16.h>
#include <cstdint>

#define EMS 1024
#define NH 16
#define HD 64
#define SEQ 2048
#define BATCH 2

// ---------------------------------------------------------------------------
// PTX helpers (non-'a' features only: ldmatrix, mma.sync, cp.async)
// ---------------------------------------------------------------------------
__device__ __forceinline__ uint32_t smem_u32(const void* p) {
    uint32_t a;
    asm("{ .reg .u64 t; cvta.to.shared.u64 t, %1; cvt.u32.u64 %0, t; }" : "=r"(a) : "l"(p));
    return a;
}
#define CP_ASYNC16(dst, src) \
    asm volatile("cp.async.cg.shared.global [%0], [%1], 16;" :: "r"(dst), "l"(src) : "memory")
#define CP_COMMIT() asm volatile("cp.async.commit_group;" ::: "memory")
#define CP_WAIT(n)  asm volatile("cp.async.wait_group %0;" :: "n"(n) : "memory")

__device__ __forceinline__ void ldsm_x4(uint32_t* r, uint32_t addr) {
    asm volatile("ldmatrix.sync.aligned.m8n8.x4.shared.b16 {%0,%1,%2,%3}, [%4];"
        : "=r"(r[0]), "=r"(r[1]), "=r"(r[2]), "=r"(r[3]) : "r"(addr));
}
__device__ __forceinline__ void ldsm_x4_t(uint32_t* r, uint32_t addr) {
    asm volatile("ldmatrix.sync.aligned.m8n8.x4.trans.shared.b16 {%0,%1,%2,%3}, [%4];"
        : "=r"(r[0]), "=r"(r[1]), "=r"(r[2]), "=r"(r[3]) : "r"(addr));
}
__device__ __forceinline__ void mma16816(float* c, const uint32_t* a, const uint32_t* b) {
    asm volatile("mma.sync.aligned.m16n8k16.row.col.f32.bf16.bf16.f32 "
        "{%0,%1,%2,%3}, {%4,%5,%6,%7}, {%8,%9}, {%0,%1,%2,%3};"
        : "+f"(c[0]), "+f"(c[1]), "+f"(c[2]), "+f"(c[3])
        : "r"(a[0]), "r"(a[1]), "r"(a[2]), "r"(a[3]), "r"(b[0]), "r"(b[1]));
}
__device__ __forceinline__ uint32_t pack_bf16x2(float lo, float hi) {
    __nv_bfloat162 t = __float22bfloat162_rn(make_float2(lo, hi));
    return *(uint32_t*)&t;
}

// ---------------------------------------------------------------------------
// Device scratch
// ---------------------------------------------------------------------------
__device__ __nv_bfloat16 g_Qh[BATCH*NH*SEQ*HD], g_Ql[BATCH*NH*SEQ*HD];
__device__ __nv_bfloat16 g_Kh[BATCH*NH*SEQ*HD], g_Kl[BATCH*NH*SEQ*HD];
__device__ __nv_bfloat16 g_Vh[BATCH*NH*SEQ*HD], g_Vl[BATCH*NH*SEQ*HD];
__device__ __nv_bfloat16 g_Eh[4096 * 1024], g_El[4096 * 1024];
__device__ __nv_bfloat16 g_Xh[4096 * 1024], g_Xl[4096 * 1024];
__device__ __nv_bfloat16 g_Wqh[1024 * 1024], g_Wql[1024 * 1024];
__device__ __nv_bfloat16 g_Wkh[1024 * 1024], g_Wkl[1024 * 1024];
__device__ __nv_bfloat16 g_Wvh[1024 * 1024], g_Wvl[1024 * 1024];

// ---------------------------------------------------------------------------
// fp32 -> bf16 hi/lo split for GEMM inputs
// ---------------------------------------------------------------------------
__global__ __launch_bounds__(256) void convert_kernel(
    const float* __restrict__ embed, const float* __restrict__ qin,
    const float* __restrict__ Wq, const float* __restrict__ Wk, const float* __restrict__ Wv)
{
    const int z = blockIdx.y;
    const float* src; __nv_bfloat16* hi; __nv_bfloat16* lo; int n4;
    switch (z) {
        case 0: src = embed; hi = g_Eh;  lo = g_El;  n4 = 4096 * 256; break;
        case 1: src = qin;   hi = g_Xh;  lo = g_Xl;  n4 = 4096 * 256; break;
        case 2: src = Wq;    hi = g_Wqh; lo = g_Wql; n4 = 1024 * 256; break;
        case 3: src = Wk;    hi = g_Wkh; lo = g_Wkl; n4 = 1024 * 256; break;
        default: src = Wv;   hi = g_Wvh; lo = g_Wvl; n4 = 1024 * 256; break;
    }
    const int t = blockIdx.x * 256 + threadIdx.x;
    if (t >= n4) return;
    float4 v = ((const float4*)src)[t];
    uint32_t h0 = pack_bf16x2(v.x, v.y);
    uint32_t h1 = pack_bf16x2(v.z, v.w);
    float r0 = v.x - __uint_as_float(h0 << 16);
    float r1 = v.y - __uint_as_float(h0 & 0xFFFF0000u);
    float r2 = v.z - __uint_as_float(h1 << 16);
    float r3 = v.w - __uint_as_float(h1 & 0xFFFF0000u);
    uint2 hv = make_uint2(h0, h1);
    uint2 lv = make_uint2(pack_bf16x2(r0, r1), pack_bf16x2(r2, r3));
    *(uint2*)(hi + (size_t)t * 4) = hv;
    *(uint2*)(lo + (size_t)t * 4) = lv;
}

// ---------------------------------------------------------------------------
// mma.sync bf16 projection: C = A @ W^T + bias, 3-term hi/lo split.
// 128x128 CTA tile, 8 warps 4(M)x2(N). Epilogue writes bf16 hi/lo QKV in
// [b,h,s,d] layout; Q is pre-scaled by 1/sqrt(64).
// ---------------------------------------------------------------------------
#define TILE_B 18432            // 128 rows * 144 B
#define BUF_B  (4 * TILE_B)

__global__ __launch_bounds__(256) void proj_mma_kernel(
    const float* __restrict__ bq, const float* __restrict__ bk, const float* __restrict__ bv)
{
    extern __shared__ char ds[];
    __shared__ float s_bias[128];

    const int tid  = threadIdx.x;
    const int wid  = tid >> 5;
    const int lane = tid & 31;
    const int z  = blockIdx.z;
    const int n0 = blockIdx.x * 128;
    const int m0 = blockIdx.y * 128;

    const __nv_bfloat16 *Ah, *Al, *Bh, *Bl; const float* bias;
    __nv_bfloat16 *oh, *ol;
    if (z == 0)      { Ah = g_Xh; Al = g_Xl; Bh = g_Wqh; Bl = g_Wql; bias = bq; oh = g_Qh; ol = g_Ql; }
    else if (z == 1) { Ah = g_Eh; Al = g_El; Bh = g_Wkh; Bl = g_Wkl; bias = bk; oh = g_Kh; ol = g_Kl; }
    else             { Ah = g_Eh; Al = g_El; Bh = g_Wvh; Bl = g_Wvl; bias = bv; oh = g_Vh; ol = g_Vl; }
    const float oscale = (z == 0) ? 0.125f : 1.0f;

    if (tid < 128) s_bias[tid] = bias[n0 + tid];

    const uint32_t smb = smem_u32(ds);
    const __nv_bfloat16* srcs[4] = {
        Ah + (size_t)m0 * 1024, Al + (size_t)m0 * 1024,
        Bh + (size_t)n0 * 1024, Bl + (size_t)n0 * 1024 };

    const int cprow = tid >> 3;
    const int cpseg = (tid & 7) * 16;

    auto issue = [&](int c) {
        const uint32_t bbase = smb + (c & 1) * BUF_B;
        const int k0 = c * 64;
        #pragma unroll
        for (int t4 = 0; t4 < 4; t4++) {
            const __nv_bfloat16* sp = srcs[t4] + k0;
            const uint32_t tbase = bbase + t4 * TILE_B;
            #pragma unroll
            for (int it = 0; it < 4; it++) {
                const int r = cprow + it * 32;
                CP_ASYNC16(tbase + r * 144 + cpseg,
                           (const void*)((const char*)(sp + (size_t)r * 1024) + cpseg));
            }
        }
        CP_COMMIT();
    };

    const int wm = (wid >> 1) * 32;
    const int wn = (wid & 1) * 64;

    float acc[2][8][4];
    #pragma unroll
    for (int mt = 0; mt < 2; mt++)
        #pragma unroll
        for (int nt = 0; nt < 8; nt++)
            #pragma unroll
            for (int e = 0; e < 4; e++) acc[mt][nt][e] = 0.f;

    const int a_row = lane & 15;
    const int a_kb  = ((lane >> 4) << 3) * 2;
    const int b_row = lane & 7;
    const int b_kb  = (((lane >> 3) & 1) << 3) * 2;
    const int b_nx  = (lane >= 16) ? 8 : 0;

    issue(0);

    for (int c = 0; c < 16; c++) {
        if (c + 1 < 16) { issue(c + 1); CP_WAIT(1); }
        else            { CP_WAIT(0); }
        __syncthreads();

        const uint32_t bbase = smb + (c & 1) * BUF_B;
        const uint32_t Abase = bbase;
        const uint32_t Wbase = bbase + 2 * TILE_B;

        #pragma unroll
        for (int ks = 0; ks < 4; ks++) {
            const int kb = ks * 32;
            uint32_t aF[2][2][4];
            #pragma unroll
            for (int src = 0; src < 2; src++)
                #pragma unroll
                for (int mt = 0; mt < 2; mt++)
                    ldsm_x4(aF[src][mt],
                            Abase + src * TILE_B + (wm + mt * 16 + a_row) * 144 + kb + a_kb);

            uint32_t bF[2][8][2];
            #pragma unroll
            for (int src = 0; src < 2; src++)
                #pragma unroll
                for (int p = 0; p < 4; p++) {
                    uint32_t r4[4];
                    ldsm_x4(r4, Wbase + src * TILE_B +
                                (wn + p * 16 + b_nx + b_row) * 144 + kb + b_kb);
                    bF[src][2 * p][0] = r4[0]; bF[src][2 * p][1] = r4[1];
                    bF[src][2 * p + 1][0] = r4[2]; bF[src][2 * p + 1][1] = r4[3];
                }

            #pragma unroll
            for (int mt = 0; mt < 2; mt++)
                #pragma unroll
                for (int nt = 0; nt < 8; nt++) {
                    mma16816(acc[mt][nt], aF[0][mt], bF[0][nt]);
                    mma16816(acc[mt][nt], aF[0][mt], bF[1][nt]);
                    mma16816(acc[mt][nt], aF[1][mt], bF[0][nt]);
                }
        }
        __syncthreads();
    }

    // Epilogue: add bias, scale (Q), split to bf16 hi/lo, write [b,h,s,d].
    const int rq = lane >> 2;
    const int cq = (lane & 3) * 2;
    #pragma unroll
    for (int mt = 0; mt < 2; mt++) {
        #pragma unroll
        for (int half = 0; half < 2; half++) {
            const int m  = m0 + wm + mt * 16 + rq + half * 8;
            const int bb = m >> 11;
            const int s  = m & (SEQ - 1);
            #pragma unroll
            for (int nt = 0; nt < 8; nt++) {
                const int nl = wn + nt * 8 + cq;
                const int n  = n0 + nl;
                const int h  = n >> 6, dd = n & 63;
                float vx = (acc[mt][nt][half * 2 + 0] + s_bias[nl])   * oscale;
                float vy = (acc[mt][nt][half * 2 + 1] + s_bias[nl+1]) * oscale;
                uint32_t hp = pack_bf16x2(vx, vy);
                float lx = vx - __uint_as_float(hp << 16);
                float ly = vy - __uint_as_float(hp & 0xFFFF0000u);
                uint32_t lp = pack_bf16x2(lx, ly);
                const size_t idx = (((size_t)(bb * NH + h) * SEQ) + s) * HD + dd;
                *(uint32_t*)(oh + idx) = hp;
                *(uint32_t*)(ol + idx) = lp;
            }
        }
    }
}

// ---------------------------------------------------------------------------
// Tensor-core flash attention.
// CTA = 128 queries x one (b,h). 8 warps, warp w owns rows [16w,16w+16).
// Key tiles of 64; K/V hi+lo in cp.async double-buffered smem (144B rows).
// S: 3-pass hi/lo bf16 MMA. PV: 3-pass; P acc->A frag conversion in registers.
// ---------------------------------------------------------------------------
#define ATILE 9216              // 64 rows * 144B
#define ASTAGE (4 * ATILE)      // Kh, Kl, Vh, Vl

__global__ __launch_bounds__(256) void attn_mma_kernel(float* __restrict__ out)
{
    extern __shared__ char ds[];
    const int tid  = threadIdx.x;
    const int w    = tid >> 5;
    const int lane = tid & 31;
    const int gid  = lane >> 2;
    const int tig  = lane & 3;
    const int bh   = blockIdx.y;
    const int q0   = blockIdx.x * 128;

    const size_t base = (size_t)bh * SEQ * HD;
    const uint32_t smb = smem_u32(ds);

    // --- Q fragments (registers, whole kernel) ---
    uint32_t qh[4][4], ql[4][4];
    {
        const __nv_bfloat16* Qh = g_Qh + base;
        const __nv_bfloat16* Ql = g_Ql + base;
        const int r0 = q0 + w * 16 + gid;
        #pragma unroll
        for (int kt = 0; kt < 4; kt++) {
            const int c0 = kt * 16 + 2 * tig;
            qh[kt][0] = *(const uint32_t*)(Qh + (size_t)r0 * HD + c0);
            qh[kt][1] = *(const uint32_t*)(Qh + (size_t)(r0 + 8) * HD + c0);
            qh[kt][2] = *(const uint32_t*)(Qh + (size_t)r0 * HD + c0 + 8);
            qh[kt][3] = *(const uint32_t*)(Qh + (size_t)(r0 + 8) * HD + c0 + 8);
            ql[kt][0] = *(const uint32_t*)(Ql + (size_t)r0 * HD + c0);
            ql[kt][1] = *(const uint32_t*)(Ql + (size_t)(r0 + 8) * HD + c0);
            ql[kt][2] = *(const uint32_t*)(Ql + (size_t)r0 * HD + c0 + 8);
            ql[kt][3] = *(const uint32_t*)(Ql + (size_t)(r0 + 8) * HD + c0 + 8);
        }
    }

    const __nv_bfloat16* tsrc[4] = { g_Kh + base, g_Kl + base, g_Vh + base, g_Vl + base };

    auto issue = [&](int c) {
        const uint32_t sb = smb + (c & 1) * ASTAGE;
        const int k0 = c * 64;
        #pragma unroll
        for (int i = 0; i < 8; i++) {
            const int ch = tid + i * 256;
            const int t4 = ch >> 9, row = (ch >> 3) & 63, seg = (ch & 7) * 16;
            CP_ASYNC16(sb + t4 * ATILE + row * 144 + seg,
                       (const void*)((const char*)(tsrc[t4] + (size_t)(k0 + row) * HD) + seg));
        }
        CP_COMMIT();
    };

    float m_r[2] = { -1e30f, -1e30f };
    float l_r[2] = { 0.f, 0.f };
    float oacc[8][4];
    #pragma unroll
    for (int j = 0; j < 8; j++)
        #pragma unroll
        for (int e = 0; e < 4; e++) oacc[j][e] = 0.f;

    const int b_row = lane & 7;
    const int b_kb  = ((lane >> 3) & 1) * 16;
    const int b_nx  = (lane & 16) ? 8 : 0;
    const int v_row = lane & 15;
    const int v_cb  = (lane & 16) ? 16 : 0;

    issue(0);

    for (int c = 0; c < 32; c++) {
        if (c + 1 < 32) { issue(c + 1); CP_WAIT(1); }
        else            { CP_WAIT(0); }
        __syncthreads();

        const uint32_t Kb = smb + (c & 1) * ASTAGE;
        const uint32_t Vb = Kb + 2 * ATILE;

        // ---- S = Q K^T (3-pass) ----
        float sacc[8][4];
        #pragma unroll
        for (int j = 0; j < 8; j++)
            #pragma unroll
            for (int e = 0; e < 4; e++) sacc[j][e] = 0.f;

        #pragma unroll
        for (int kt = 0; kt < 4; kt++) {
            const int kb = kt * 32;
            uint32_t bKh[4][4], bKl[4][4];
            #pragma unroll
            for (int p = 0; p < 4; p++) {
                ldsm_x4(bKh[p], Kb + (p * 16 + b_nx + b_row) * 144 + kb + b_kb);
                ldsm_x4(bKl[p], Kb + ATILE + (p * 16 + b_nx + b_row) * 144 + kb + b_kb);
            }
            #pragma unroll
            for (int j = 0; j < 8; j++) {
                const uint32_t* ph = &bKh[j >> 1][(j & 1) * 2];
                const uint32_t* pl = &bKl[j >> 1][(j & 1) * 2];
                mma16816(sacc[j], qh[kt], ph);
                mma16816(sacc[j], qh[kt], pl);
                mma16816(sacc[j], ql[kt], ph);
            }
        }

        // ---- online softmax ----
        float mx0 = -1e30f, mx1 = -1e30f;
        #pragma unroll
        for (int j = 0; j < 8; j++) {
            mx0 = fmaxf(mx0, fmaxf(sacc[j][0], sacc[j][1]));
            mx1 = fmaxf(mx1, fmaxf(sacc[j][2], sacc[j][3]));
        }
        mx0 = fmaxf(mx0, __shfl_xor_sync(0xffffffffu, mx0, 1));
        mx0 = fmaxf(mx0, __shfl_xor_sync(0xffffffffu, mx0, 2));
        mx1 = fmaxf(mx1, __shfl_xor_sync(0xffffffffu, mx1, 1));
        mx1 = fmaxf(mx1, __shfl_xor_sync(0xffffffffu, mx1, 2));

        const float mn0 = fmaxf(m_r[0], mx0);
        const float mn1 = fmaxf(m_r[1], mx1);
        const float al0 = __expf(m_r[0] - mn0);
        const float al1 = __expf(m_r[1] - mn1);
        m_r[0] = mn0; m_r[1] = mn1;

        uint32_t pa_h[4][4], pa_l[4][4];
        float rs0 = 0.f, rs1 = 0.f;
        #pragma unroll
        for (int j = 0; j < 8; j++) {
            float p0 = __expf(sacc[j][0] - mn0);
            float p1 = __expf(sacc[j][1] - mn0);
            float p2 = __expf(sacc[j][2] - mn1);
            float p3 = __expf(sacc[j][3] - mn1);
            rs0 += p0 + p1; rs1 += p2 + p3;
            const int kt2 = j >> 1, rb = (j & 1) * 2;
            uint32_t h01 = pack_bf16x2(p0, p1);
            uint32_t h23 = pack_bf16x2(p2, p3);
            pa_h[kt2][rb + 0] = h01;
            pa_h[kt2][rb + 1] = h23;
            float e0 = p0 - __uint_as_float(h01 << 16);
            float e1 = p1 - __uint_as_float(h01 & 0xFFFF0000u);
            float e2 = p2 - __uint_as_float(h23 << 16);
            float e3 = p3 - __uint_as_float(h23 & 0xFFFF0000u);
            pa_l[kt2][rb + 0] = pack_bf16x2(e0, e1);
            pa_l[kt2][rb + 1] = pack_bf16x2(e2, e3);
        }
        rs0 += __shfl_xor_sync(0xffffffffu, rs0, 1);
        rs0 += __shfl_xor_sync(0xffffffffu, rs0, 2);
        rs1 += __shfl_xor_sync(0xffffffffu, rs1, 1);
        rs1 += __shfl_xor_sync(0xffffffffu, rs1, 2);
        l_r[0] = l_r[0] * al0 + rs0;
        l_r[1] = l_r[1] * al1 + rs1;

        #pragma unroll
        for (int j = 0; j < 8; j++) {
            oacc[j][0] *= al0; oacc[j][1] *= al0;
            oacc[j][2] *= al1; oacc[j][3] *= al1;
        }

        // ---- O += P V (3-pass) ----
        #pragma unroll
        for (int kt2 = 0; kt2 < 4; kt2++) {
            uint32_t bVh[4][4], bVl[4][4];
            #pragma unroll
            for (int p = 0; p < 4; p++) {
                ldsm_x4_t(bVh[p], Vb + (kt2 * 16 + v_row) * 144 + p * 32 + v_cb);
                ldsm_x4_t(bVl[p], Vb + ATILE + (kt2 * 16 + v_row) * 144 + p * 32 + v_cb);
            }
            #pragma unroll
            for (int j = 0; j < 8; j++) {
                const uint32_t* vh = &bVh[j >> 1][(j & 1) * 2];
                const uint32_t* vl = &bVl[j >> 1][(j & 1) * 2];
                mma16816(oacc[j], pa_h[kt2], vh);
                mma16816(oacc[j], pa_h[kt2], vl);
                mma16816(oacc[j], pa_l[kt2], vh);
            }
        }
        __syncthreads();
    }

    // ---- epilogue: normalize, write [b, q, h*64+d] ----
    const int bb = bh >> 4;
    const int h  = bh & 15;
    const float inv0 = 1.f / l_r[0];
    const float inv1 = 1.f / l_r[1];
    const int qr = q0 + w * 16 + gid;
    #pragma unroll
    for (int j = 0; j < 8; j++) {
        const int dd = 8 * j + 2 * tig;
        float2 v0 = make_float2(oacc[j][0] * inv0, oacc[j][1] * inv0);
        float2 v1 = make_float2(oacc[j][2] * inv1, oacc[j][3] * inv1);
        *(float2*)&out[((size_t)(bb * SEQ + qr)) * EMS + h * HD + dd]       = v0;
        *(float2*)&out[((size_t)(bb * SEQ + qr + 8)) * EMS + h * HD + dd]   = v1;
    }
}

// ---------------------------------------------------------------------------
extern "C" void kernel_launch(void* const* d_in, const int* in_sizes, int n_in,
                              void* d_out, int out_size)
{
    const float* embed = (const float*)d_in[0];
    const float* q     = (const float*)d_in[1];
    const float* Wk    = (const float*)d_in[2];
    const float* bk    = (const float*)d_in[3];
    const float* Wq    = (const float*)d_in[4];
    const float* bq    = (const float*)d_in[5];
    const float* Wv    = (const float*)d_in[6];
    const float* bv    = (const float*)d_in[7];
    float* out = (float*)d_out;

    convert_kernel<<<dim3(4096, 5), 256>>>(embed, q, Wq, Wk, Wv);

    cudaFuncSetAttribute(proj_mma_kernel, cudaFuncAttributeMaxDynamicSharedMemorySize, 2 * BUF_B);
    proj_mma_kernel<<<dim3(EMS / 128, (BATCH * SEQ) / 128, 3), 256, 2 * BUF_B>>>(bq, bk, bv);

    cudaFuncSetAttribute(attn_mma_kernel, cudaFuncAttributeMaxDynamicSharedMemorySize, 2 * ASTAGE);
    attn_mma_kernel<<<dim3(SEQ / 128, BATCH * NH), 256, 2 * ASTAGE>>>(out);
}

// round 6
// speedup vs baseline: 3.4102x; 1.1862x over previous
#include <cuda_runtime.h>
#include <cuda_fp16.h>
#include <cuda_bf16.h>
#include <cstdint>

#define EMS 1024
#define NH 16
#define HD 64
#define SEQ 2048
#define BATCH 2

// ---------------------------------------------------------------------------
// PTX helpers
// ---------------------------------------------------------------------------
__device__ __forceinline__ uint32_t smem_u32(const void* p) {
    uint32_t a;
    asm("{ .reg .u64 t; cvta.to.shared.u64 t, %1; cvt.u32.u64 %0, t; }" : "=r"(a) : "l"(p));
    return a;
}
#define CP_ASYNC16(dst, src) \
    asm volatile("cp.async.cg.shared.global [%0], [%1], 16;" :: "r"(dst), "l"(src) : "memory")
#define CP_COMMIT() asm volatile("cp.async.commit_group;" ::: "memory")
#define CP_WAIT(n)  asm volatile("cp.async.wait_group %0;" :: "n"(n) : "memory")

__device__ __forceinline__ void ldsm_x4(uint32_t* r, uint32_t addr) {
    asm volatile("ldmatrix.sync.aligned.m8n8.x4.shared.b16 {%0,%1,%2,%3}, [%4];"
        : "=r"(r[0]), "=r"(r[1]), "=r"(r[2]), "=r"(r[3]) : "r"(addr));
}
__device__ __forceinline__ void ldsm_x4_t(uint32_t* r, uint32_t addr) {
    asm volatile("ldmatrix.sync.aligned.m8n8.x4.trans.shared.b16 {%0,%1,%2,%3}, [%4];"
        : "=r"(r[0]), "=r"(r[1]), "=r"(r[2]), "=r"(r[3]) : "r"(addr));
}
__device__ __forceinline__ void mma16816bf(float* c, const uint32_t* a, const uint32_t* b) {
    asm volatile("mma.sync.aligned.m16n8k16.row.col.f32.bf16.bf16.f32 "
        "{%0,%1,%2,%3}, {%4,%5,%6,%7}, {%8,%9}, {%0,%1,%2,%3};"
        : "+f"(c[0]), "+f"(c[1]), "+f"(c[2]), "+f"(c[3])
        : "r"(a[0]), "r"(a[1]), "r"(a[2]), "r"(a[3]), "r"(b[0]), "r"(b[1]));
}
__device__ __forceinline__ void mma16816h(float* c, const uint32_t* a, const uint32_t* b) {
    asm volatile("mma.sync.aligned.m16n8k16.row.col.f32.f16.f16.f32 "
        "{%0,%1,%2,%3}, {%4,%5,%6,%7}, {%8,%9}, {%0,%1,%2,%3};"
        : "+f"(c[0]), "+f"(c[1]), "+f"(c[2]), "+f"(c[3])
        : "r"(a[0]), "r"(a[1]), "r"(a[2]), "r"(a[3]), "r"(b[0]), "r"(b[1]));
}
__device__ __forceinline__ uint32_t pack_bf16x2(float lo, float hi) {
    __nv_bfloat162 t = __float22bfloat162_rn(make_float2(lo, hi));
    return *(uint32_t*)&t;
}
__device__ __forceinline__ uint32_t pack_h2(float lo, float hi) {
    __half2 t = __floats2half2_rn(lo, hi);
    return *(uint32_t*)&t;
}

// ---------------------------------------------------------------------------
// Device scratch
// ---------------------------------------------------------------------------
__device__ __half g_Qh[BATCH*NH*SEQ*HD], g_Ql[BATCH*NH*SEQ*HD];
__device__ __half g_Kh[BATCH*NH*SEQ*HD];
__device__ __half g_Vh[BATCH*NH*SEQ*HD];
__device__ __nv_bfloat16 g_Eh[4096 * 1024], g_El[4096 * 1024];
__device__ __nv_bfloat16 g_Xh[4096 * 1024], g_Xl[4096 * 1024];
__device__ __nv_bfloat16 g_Wqh[1024 * 1024], g_Wql[1024 * 1024];
__device__ __nv_bfloat16 g_Wkh[1024 * 1024], g_Wkl[1024 * 1024];
__device__ __nv_bfloat16 g_Wvh[1024 * 1024], g_Wvl[1024 * 1024];

// ---------------------------------------------------------------------------
// fp32 -> bf16 hi/lo split for GEMM inputs
// ---------------------------------------------------------------------------
__global__ __launch_bounds__(256) void convert_kernel(
    const float* __restrict__ embed, const float* __restrict__ qin,
    const float* __restrict__ Wq, const float* __restrict__ Wk, const float* __restrict__ Wv)
{
    const int z = blockIdx.y;
    const float* src; __nv_bfloat16* hi; __nv_bfloat16* lo; int n4;
    switch (z) {
        case 0: src = embed; hi = g_Eh;  lo = g_El;  n4 = 4096 * 256; break;
        case 1: src = qin;   hi = g_Xh;  lo = g_Xl;  n4 = 4096 * 256; break;
        case 2: src = Wq;    hi = g_Wqh; lo = g_Wql; n4 = 1024 * 256; break;
        case 3: src = Wk;    hi = g_Wkh; lo = g_Wkl; n4 = 1024 * 256; break;
        default: src = Wv;   hi = g_Wvh; lo = g_Wvl; n4 = 1024 * 256; break;
    }
    const int t = blockIdx.x * 256 + threadIdx.x;
    if (t >= n4) return;
    float4 v = ((const float4*)src)[t];
    uint32_t h0 = pack_bf16x2(v.x, v.y);
    uint32_t h1 = pack_bf16x2(v.z, v.w);
    float r0 = v.x - __uint_as_float(h0 << 16);
    float r1 = v.y - __uint_as_float(h0 & 0xFFFF0000u);
    float r2 = v.z - __uint_as_float(h1 << 16);
    float r3 = v.w - __uint_as_float(h1 & 0xFFFF0000u);
    *(uint2*)(hi + (size_t)t * 4) = make_uint2(h0, h1);
    *(uint2*)(lo + (size_t)t * 4) = make_uint2(pack_bf16x2(r0, r1), pack_bf16x2(r2, r3));
}

// ---------------------------------------------------------------------------
// mma.sync bf16 projection (3-pass hi/lo). Epilogue: Q -> fp16 hi/lo scaled,
// K/V -> single fp16, all in [b,h,s,d].
// ---------------------------------------------------------------------------
#define TILE_B 18432            // 128 rows * 144 B
#define BUF_B  (4 * TILE_B)

__global__ __launch_bounds__(256) void proj_mma_kernel(
    const float* __restrict__ bq, const float* __restrict__ bk, const float* __restrict__ bv)
{
    extern __shared__ char ds[];
    __shared__ float s_bias[128];

    const int tid  = threadIdx.x;
    const int wid  = tid >> 5;
    const int lane = tid & 31;
    const int z  = blockIdx.z;
    const int n0 = blockIdx.x * 128;
    const int m0 = blockIdx.y * 128;

    const __nv_bfloat16 *Ah, *Al, *Bh, *Bl; const float* bias;
    if (z == 0)      { Ah = g_Xh; Al = g_Xl; Bh = g_Wqh; Bl = g_Wql; bias = bq; }
    else if (z == 1) { Ah = g_Eh; Al = g_El; Bh = g_Wkh; Bl = g_Wkl; bias = bk; }
    else             { Ah = g_Eh; Al = g_El; Bh = g_Wvh; Bl = g_Wvl; bias = bv; }

    if (tid < 128) s_bias[tid] = bias[n0 + tid];

    const uint32_t smb = smem_u32(ds);
    const __nv_bfloat16* srcs[4] = {
        Ah + (size_t)m0 * 1024, Al + (size_t)m0 * 1024,
        Bh + (size_t)n0 * 1024, Bl + (size_t)n0 * 1024 };

    const int cprow = tid >> 3;
    const int cpseg = (tid & 7) * 16;

    auto issue = [&](int c) {
        const uint32_t bbase = smb + (c & 1) * BUF_B;
        const int k0 = c * 64;
        #pragma unroll
        for (int t4 = 0; t4 < 4; t4++) {
            const __nv_bfloat16* sp = srcs[t4] + k0;
            const uint32_t tbase = bbase + t4 * TILE_B;
            #pragma unroll
            for (int it = 0; it < 4; it++) {
                const int r = cprow + it * 32;
                CP_ASYNC16(tbase + r * 144 + cpseg,
                           (const void*)((const char*)(sp + (size_t)r * 1024) + cpseg));
            }
        }
        CP_COMMIT();
    };

    const int wm = (wid >> 1) * 32;
    const int wn = (wid & 1) * 64;

    float acc[2][8][4];
    #pragma unroll
    for (int mt = 0; mt < 2; mt++)
        #pragma unroll
        for (int nt = 0; nt < 8; nt++)
            #pragma unroll
            for (int e = 0; e < 4; e++) acc[mt][nt][e] = 0.f;

    const int a_row = lane & 15;
    const int a_kb  = ((lane >> 4) << 3) * 2;
    const int b_row = lane & 7;
    const int b_kb  = (((lane >> 3) & 1) << 3) * 2;
    const int b_nx  = (lane >= 16) ? 8 : 0;

    issue(0);

    for (int c = 0; c < 16; c++) {
        if (c + 1 < 16) { issue(c + 1); CP_WAIT(1); }
        else            { CP_WAIT(0); }
        __syncthreads();

        const uint32_t bbase = smb + (c & 1) * BUF_B;
        const uint32_t Abase = bbase;
        const uint32_t Wbase = bbase + 2 * TILE_B;

        #pragma unroll
        for (int ks = 0; ks < 4; ks++) {
            const int kb = ks * 32;
            uint32_t aF[2][2][4];
            #pragma unroll
            for (int src = 0; src < 2; src++)
                #pragma unroll
                for (int mt = 0; mt < 2; mt++)
                    ldsm_x4(aF[src][mt],
                            Abase + src * TILE_B + (wm + mt * 16 + a_row) * 144 + kb + a_kb);

            uint32_t bF[2][8][2];
            #pragma unroll
            for (int src = 0; src < 2; src++)
                #pragma unroll
                for (int p = 0; p < 4; p++) {
                    uint32_t r4[4];
                    ldsm_x4(r4, Wbase + src * TILE_B +
                                (wn + p * 16 + b_nx + b_row) * 144 + kb + b_kb);
                    bF[src][2 * p][0] = r4[0]; bF[src][2 * p][1] = r4[1];
                    bF[src][2 * p + 1][0] = r4[2]; bF[src][2 * p + 1][1] = r4[3];
                }

            #pragma unroll
            for (int mt = 0; mt < 2; mt++)
                #pragma unroll
                for (int nt = 0; nt < 8; nt++) {
                    mma16816bf(acc[mt][nt], aF[0][mt], bF[0][nt]);
                    mma16816bf(acc[mt][nt], aF[0][mt], bF[1][nt]);
                    mma16816bf(acc[mt][nt], aF[1][mt], bF[0][nt]);
                }
        }
        __syncthreads();
    }

    // Epilogue
    const int rq = lane >> 2;
    const int cq = (lane & 3) * 2;
    #pragma unroll
    for (int mt = 0; mt < 2; mt++) {
        #pragma unroll
        for (int half = 0; half < 2; half++) {
            const int m  = m0 + wm + mt * 16 + rq + half * 8;
            const int bb = m >> 11;
            const int s  = m & (SEQ - 1);
            #pragma unroll
            for (int nt = 0; nt < 8; nt++) {
                const int nl = wn + nt * 8 + cq;
                const int n  = n0 + nl;
                const int h  = n >> 6, dd = n & 63;
                float vx = acc[mt][nt][half * 2 + 0] + s_bias[nl];
                float vy = acc[mt][nt][half * 2 + 1] + s_bias[nl + 1];
                const size_t idx = (((size_t)(bb * NH + h) * SEQ) + s) * HD + dd;
                if (z == 0) {
                    vx *= 0.125f; vy *= 0.125f;
                    __half hx = __float2half_rn(vx), hy = __float2half_rn(vy);
                    float lx = vx - __half2float(hx);
                    float ly = vy - __half2float(hy);
                    *(uint32_t*)(g_Qh + idx) = pack_h2(__half2float(hx), __half2float(hy));
                    *(uint32_t*)(g_Ql + idx) = pack_h2(lx, ly);
                } else {
                    __half* dst = (z == 1) ? g_Kh : g_Vh;
                    *(uint32_t*)(dst + idx) = pack_h2(vx, vy);
                }
            }
        }
    }
}

// ---------------------------------------------------------------------------
// Tensor-core flash attention, fp16 2-pass.
// CTA = 128 q x (b,h), 8 warps x 16 rows. Key tiles of 64.
// S: (Qh + Ql) x K  (2 MMAs, K single fp16)
// PV: (Ph + Pl) x V (2 MMAs, V single fp16)
// ---------------------------------------------------------------------------
#define ATILE 9216              // 64 rows * 144B
#define ASTAGE (2 * ATILE)      // K, V

__global__ __launch_bounds__(256) void attn_mma_kernel(float* __restrict__ out)
{
    extern __shared__ char ds[];
    const int tid  = threadIdx.x;
    const int w    = tid >> 5;
    const int lane = tid & 31;
    const int gid  = lane >> 2;
    const int tig  = lane & 3;
    const int bh   = blockIdx.y;
    const int q0   = blockIdx.x * 128;

    const size_t base = (size_t)bh * SEQ * HD;
    const uint32_t smb = smem_u32(ds);

    // Q fragments (fp16 hi/lo), registers for the whole kernel
    uint32_t qh[4][4], ql[4][4];
    {
        const __half* Qh = g_Qh + base;
        const __half* Ql = g_Ql + base;
        const int r0 = q0 + w * 16 + gid;
        #pragma unroll
        for (int kt = 0; kt < 4; kt++) {
            const int c0 = kt * 16 + 2 * tig;
            qh[kt][0] = *(const uint32_t*)(Qh + (size_t)r0 * HD + c0);
            qh[kt][1] = *(const uint32_t*)(Qh + (size_t)(r0 + 8) * HD + c0);
            qh[kt][2] = *(const uint32_t*)(Qh + (size_t)r0 * HD + c0 + 8);
            qh[kt][3] = *(const uint32_t*)(Qh + (size_t)(r0 + 8) * HD + c0 + 8);
            ql[kt][0] = *(const uint32_t*)(Ql + (size_t)r0 * HD + c0);
            ql[kt][1] = *(const uint32_t*)(Ql + (size_t)(r0 + 8) * HD + c0);
            ql[kt][2] = *(const uint32_t*)(Ql + (size_t)r0 * HD + c0 + 8);
            ql[kt][3] = *(const uint32_t*)(Ql + (size_t)(r0 + 8) * HD + c0 + 8);
        }
    }

    const __half* tsrc[2] = { g_Kh + base, g_Vh + base };

    auto issue = [&](int c) {
        const uint32_t sb = smb + (c & 1) * ASTAGE;
        const int k0 = c * 64;
        #pragma unroll
        for (int i = 0; i < 4; i++) {
            const int ch = tid + i * 256;
            const int t2 = ch >> 9, row = (ch >> 3) & 63, seg = (ch & 7) * 16;
            CP_ASYNC16(sb + t2 * ATILE + row * 144 + seg,
                       (const void*)((const char*)(tsrc[t2] + (size_t)(k0 + row) * HD) + seg));
        }
        CP_COMMIT();
    };

    float m_r[2] = { -1e30f, -1e30f };
    float l_r[2] = { 0.f, 0.f };
    float oacc[8][4];
    #pragma unroll
    for (int j = 0; j < 8; j++)
        #pragma unroll
        for (int e = 0; e < 4; e++) oacc[j][e] = 0.f;

    const int b_row = lane & 7;
    const int b_kb  = ((lane >> 3) & 1) * 16;
    const int b_nx  = (lane & 16) ? 8 : 0;
    const int v_row = lane & 15;
    const int v_cb  = (lane & 16) ? 16 : 0;

    issue(0);

    for (int c = 0; c < 32; c++) {
        if (c + 1 < 32) { issue(c + 1); CP_WAIT(1); }
        else            { CP_WAIT(0); }
        __syncthreads();

        const uint32_t Kb = smb + (c & 1) * ASTAGE;
        const uint32_t Vb = Kb + ATILE;

        // ---- S = Q K^T (2-pass) ----
        float sacc[8][4];
        #pragma unroll
        for (int j = 0; j < 8; j++)
            #pragma unroll
            for (int e = 0; e < 4; e++) sacc[j][e] = 0.f;

        #pragma unroll
        for (int kt = 0; kt < 4; kt++) {
            const int kb = kt * 32;
            uint32_t bK[4][4];
            #pragma unroll
            for (int p = 0; p < 4; p++)
                ldsm_x4(bK[p], Kb + (p * 16 + b_nx + b_row) * 144 + kb + b_kb);
            #pragma unroll
            for (int j = 0; j < 8; j++) {
                const uint32_t* pk = &bK[j >> 1][(j & 1) * 2];
                mma16816h(sacc[j], qh[kt], pk);
                mma16816h(sacc[j], ql[kt], pk);
            }
        }

        // ---- online softmax ----
        float mx0 = -1e30f, mx1 = -1e30f;
        #pragma unroll
        for (int j = 0; j < 8; j++) {
            mx0 = fmaxf(mx0, fmaxf(sacc[j][0], sacc[j][1]));
            mx1 = fmaxf(mx1, fmaxf(sacc[j][2], sacc[j][3]));
        }
        mx0 = fmaxf(mx0, __shfl_xor_sync(0xffffffffu, mx0, 1));
        mx0 = fmaxf(mx0, __shfl_xor_sync(0xffffffffu, mx0, 2));
        mx1 = fmaxf(mx1, __shfl_xor_sync(0xffffffffu, mx1, 1));
        mx1 = fmaxf(mx1, __shfl_xor_sync(0xffffffffu, mx1, 2));

        const float mn0 = fmaxf(m_r[0], mx0);
        const float mn1 = fmaxf(m_r[1], mx1);
        const float al0 = __expf(m_r[0] - mn0);
        const float al1 = __expf(m_r[1] - mn1);
        m_r[0] = mn0; m_r[1] = mn1;

        uint32_t pa_h[4][4], pa_l[4][4];
        float rs0 = 0.f, rs1 = 0.f;
        #pragma unroll
        for (int j = 0; j < 8; j++) {
            float p0 = __expf(sacc[j][0] - mn0);
            float p1 = __expf(sacc[j][1] - mn0);
            float p2 = __expf(sacc[j][2] - mn1);
            float p3 = __expf(sacc[j][3] - mn1);
            rs0 += p0 + p1; rs1 += p2 + p3;
            const int kt2 = j >> 1, rb = (j & 1) * 2;
            __half h0 = __float2half_rn(p0), h1 = __float2half_rn(p1);
            __half h2 = __float2half_rn(p2), h3 = __float2half_rn(p3);
            pa_h[kt2][rb + 0] = pack_h2(__half2float(h0), __half2float(h1));
            pa_h[kt2][rb + 1] = pack_h2(__half2float(h2), __half2float(h3));
            pa_l[kt2][rb + 0] = pack_h2(p0 - __half2float(h0), p1 - __half2float(h1));
            pa_l[kt2][rb + 1] = pack_h2(p2 - __half2float(h2), p3 - __half2float(h3));
        }
        rs0 += __shfl_xor_sync(0xffffffffu, rs0, 1);
        rs0 += __shfl_xor_sync(0xffffffffu, rs0, 2);
        rs1 += __shfl_xor_sync(0xffffffffu, rs1, 1);
        rs1 += __shfl_xor_sync(0xffffffffu, rs1, 2);
        l_r[0] = l_r[0] * al0 + rs0;
        l_r[1] = l_r[1] * al1 + rs1;

        #pragma unroll
        for (int j = 0; j < 8; j++) {
            oacc[j][0] *= al0; oacc[j][1] *= al0;
            oacc[j][2] *= al1; oacc[j][3] *= al1;
        }

        // ---- O += P V (2-pass) ----
        #pragma unroll
        for (int kt2 = 0; kt2 < 4; kt2++) {
            uint32_t bV[4][4];
            #pragma unroll
            for (int p = 0; p < 4; p++)
                ldsm_x4_t(bV[p], Vb + (kt2 * 16 + v_row) * 144 + p * 32 + v_cb);
            #pragma unroll
            for (int j = 0; j < 8; j++) {
                const uint32_t* pv = &bV[j >> 1][(j & 1) * 2];
                mma16816h(oacc[j], pa_h[kt2], pv);
                mma16816h(oacc[j], pa_l[kt2], pv);
            }
        }
        __syncthreads();
    }

    // ---- epilogue ----
    const int bb = bh >> 4;
    const int h  = bh & 15;
    const float inv0 = 1.f / l_r[0];
    const float inv1 = 1.f / l_r[1];
    const int qr = q0 + w * 16 + gid;
    #pragma unroll
    for (int j = 0; j < 8; j++) {
        const int dd = 8 * j + 2 * tig;
        float2 v0 = make_float2(oacc[j][0] * inv0, oacc[j][1] * inv0);
        float2 v1 = make_float2(oacc[j][2] * inv1, oacc[j][3] * inv1);
        *(float2*)&out[((size_t)(bb * SEQ + qr)) * EMS + h * HD + dd]     = v0;
        *(float2*)&out[((size_t)(bb * SEQ + qr + 8)) * EMS + h * HD + dd] = v1;
    }
}

// ---------------------------------------------------------------------------
extern "C" void kernel_launch(void* const* d_in, const int* in_sizes, int n_in,
                              void* d_out, int out_size)
{
    const float* embed = (const float*)d_in[0];
    const float* q     = (const float*)d_in[1];
    const float* Wk    = (const float*)d_in[2];
    const float* bk    = (const float*)d_in[3];
    const float* Wq    = (const float*)d_in[4];
    const float* bq    = (const float*)d_in[5];
    const float* Wv    = (const float*)d_in[6];
    const float* bv    = (const float*)d_in[7];
    float* out = (float*)d_out;

    convert_kernel<<<dim3(4096, 5), 256>>>(embed, q, Wq, Wk, Wv);

    cudaFuncSetAttribute(proj_mma_kernel, cudaFuncAttributeMaxDynamicSharedMemorySize, 2 * BUF_B);
    proj_mma_kernel<<<dim3(EMS / 128, (BATCH * SEQ) / 128, 3), 256, 2 * BUF_B>>>(bq, bk, bv);

    cudaFuncSetAttribute(attn_mma_kernel, cudaFuncAttributeMaxDynamicSharedMemorySize, 2 * ASTAGE);
    attn_mma_kernel<<<dim3(SEQ / 128, BATCH * NH), 256, 2 * ASTAGE>>>(out);
}

// round 7
// speedup vs baseline: 6.0204x; 1.7654x over previous
#include <cuda_runtime.h>
#include <cuda_fp16.h>
#include <cstdint>

#define EMS 1024
#define NH 16
#define HD 64
#define SEQ 2048
#define BATCH 2

// ---------------------------------------------------------------------------
// PTX helpers
// ---------------------------------------------------------------------------
__device__ __forceinline__ uint32_t smem_u32(const void* p) {
    uint32_t a;
    asm("{ .reg .u64 t; cvta.to.shared.u64 t, %1; cvt.u32.u64 %0, t; }" : "=r"(a) : "l"(p));
    return a;
}
#define CP_ASYNC16(dst, src) \
    asm volatile("cp.async.cg.shared.global [%0], [%1], 16;" :: "r"(dst), "l"(src) : "memory")
#define CP_COMMIT() asm volatile("cp.async.commit_group;" ::: "memory")
#define CP_WAIT(n)  asm volatile("cp.async.wait_group %0;" :: "n"(n) : "memory")

__device__ __forceinline__ void ldsm_x4(uint32_t* r, uint32_t addr) {
    asm volatile("ldmatrix.sync.aligned.m8n8.x4.shared.b16 {%0,%1,%2,%3}, [%4];"
        : "=r"(r[0]), "=r"(r[1]), "=r"(r[2]), "=r"(r[3]) : "r"(addr));
}
__device__ __forceinline__ void ldsm_x4_t(uint32_t* r, uint32_t addr) {
    asm volatile("ldmatrix.sync.aligned.m8n8.x4.trans.shared.b16 {%0,%1,%2,%3}, [%4];"
        : "=r"(r[0]), "=r"(r[1]), "=r"(r[2]), "=r"(r[3]) : "r"(addr));
}
__device__ __forceinline__ void mma16816h(float* c, const uint32_t* a, const uint32_t* b) {
    asm volatile("mma.sync.aligned.m16n8k16.row.col.f32.f16.f16.f32 "
        "{%0,%1,%2,%3}, {%4,%5,%6,%7}, {%8,%9}, {%0,%1,%2,%3};"
        : "+f"(c[0]), "+f"(c[1]), "+f"(c[2]), "+f"(c[3])
        : "r"(a[0]), "r"(a[1]), "r"(a[2]), "r"(a[3]), "r"(b[0]), "r"(b[1]));
}
__device__ __forceinline__ uint32_t pack_h2(float lo, float hi) {
    __half2 t = __floats2half2_rn(lo, hi);
    return *(uint32_t*)&t;
}

// ---------------------------------------------------------------------------
// Device scratch (all fp16 now)
// ---------------------------------------------------------------------------
__device__ __half g_Q16[BATCH*NH*SEQ*HD];   // pre-scaled by 0.125
__device__ __half g_K16[BATCH*NH*SEQ*HD];
__device__ __half g_V16[BATCH*NH*SEQ*HD];
__device__ __half g_E16[4096 * 1024];
__device__ __half g_X16[4096 * 1024];
__device__ __half g_Wq16[1024 * 1024], g_Wk16[1024 * 1024], g_Wv16[1024 * 1024];

// ---------------------------------------------------------------------------
// fp32 -> fp16 convert
// ---------------------------------------------------------------------------
__global__ __launch_bounds__(256) void convert_kernel(
    const float* __restrict__ embed, const float* __restrict__ qin,
    const float* __restrict__ Wq, const float* __restrict__ Wk, const float* __restrict__ Wv)
{
    const int z = blockIdx.y;
    const float* src; __half* dst; int n4;
    switch (z) {
        case 0: src = embed; dst = g_E16;  n4 = 4096 * 256; break;
        case 1: src = qin;   dst = g_X16;  n4 = 4096 * 256; break;
        case 2: src = Wq;    dst = g_Wq16; n4 = 1024 * 256; break;
        case 3: src = Wk;    dst = g_Wk16; n4 = 1024 * 256; break;
        default: src = Wv;   dst = g_Wv16; n4 = 1024 * 256; break;
    }
    const int t = blockIdx.x * 256 + threadIdx.x;
    if (t >= n4) return;
    float4 v = ((const float4*)src)[t];
    *(uint2*)(dst + (size_t)t * 4) = make_uint2(pack_h2(v.x, v.y), pack_h2(v.z, v.w));
}

// ---------------------------------------------------------------------------
// fp16 1-pass projection: C = A @ W^T + bias. 128x128 CTA tile, 8 warps 4x2.
// 2 tiles/chunk (A, W), 2-stage cp.async, race-free wait->sync->issue order.
// Epilogue writes fp16 QKV in [b,h,s,d]; Q pre-scaled 0.125.
// ---------------------------------------------------------------------------
#define TILE_B 18432            // 128 rows * 144 B
#define BUF_B  (2 * TILE_B)     // A, W

__global__ __launch_bounds__(256, 2) void proj_mma_kernel(
    const float* __restrict__ bq, const float* __restrict__ bk, const float* __restrict__ bv)
{
    extern __shared__ char ds[];
    __shared__ float s_bias[128];

    const int tid  = threadIdx.x;
    const int wid  = tid >> 5;
    const int lane = tid & 31;
    const int z  = blockIdx.z;
    const int n0 = blockIdx.x * 128;
    const int m0 = blockIdx.y * 128;

    const __half *A, *W; const float* bias;
    if (z == 0)      { A = g_X16; W = g_Wq16; bias = bq; }
    else if (z == 1) { A = g_E16; W = g_Wk16; bias = bk; }
    else             { A = g_E16; W = g_Wv16; bias = bv; }

    if (tid < 128) s_bias[tid] = bias[n0 + tid];

    const uint32_t smb = smem_u32(ds);
    const __half* srcs[2] = { A + (size_t)m0 * 1024, W + (size_t)n0 * 1024 };

    const int cprow = tid >> 3;
    const int cpseg = (tid & 7) * 16;

    auto issue = [&](int c) {
        const uint32_t bbase = smb + (c & 1) * BUF_B;
        const int k0 = c * 64;
        #pragma unroll
        for (int t2 = 0; t2 < 2; t2++) {
            const __half* sp = srcs[t2] + k0;
            const uint32_t tbase = bbase + t2 * TILE_B;
            #pragma unroll
            for (int it = 0; it < 4; it++) {
                const int r = cprow + it * 32;
                CP_ASYNC16(tbase + r * 144 + cpseg,
                           (const void*)((const char*)(sp + (size_t)r * 1024) + cpseg));
            }
        }
        CP_COMMIT();
    };

    const int wm = (wid >> 1) * 32;
    const int wn = (wid & 1) * 64;

    float acc[2][8][4];
    #pragma unroll
    for (int mt = 0; mt < 2; mt++)
        #pragma unroll
        for (int nt = 0; nt < 8; nt++)
            #pragma unroll
            for (int e = 0; e < 4; e++) acc[mt][nt][e] = 0.f;

    const int a_row = lane & 15;
    const int a_kb  = ((lane >> 4) << 3) * 2;
    const int b_row = lane & 7;
    const int b_kb  = (((lane >> 3) & 1) << 3) * 2;
    const int b_nx  = (lane >= 16) ? 8 : 0;

    issue(0);

    for (int c = 0; c < 16; c++) {
        CP_WAIT(0);
        __syncthreads();
        if (c + 1 < 16) issue(c + 1);   // overlaps with compute below

        const uint32_t bbase = smb + (c & 1) * BUF_B;
        const uint32_t Abase = bbase;
        const uint32_t Wbase = bbase + TILE_B;

        #pragma unroll
        for (int ks = 0; ks < 4; ks++) {
            const int kb = ks * 32;
            uint32_t aF[2][4];
            #pragma unroll
            for (int mt = 0; mt < 2; mt++)
                ldsm_x4(aF[mt], Abase + (wm + mt * 16 + a_row) * 144 + kb + a_kb);

            uint32_t bF[8][2];
            #pragma unroll
            for (int p = 0; p < 4; p++) {
                uint32_t r4[4];
                ldsm_x4(r4, Wbase + (wn + p * 16 + b_nx + b_row) * 144 + kb + b_kb);
                bF[2 * p][0] = r4[0];     bF[2 * p][1] = r4[1];
                bF[2 * p + 1][0] = r4[2]; bF[2 * p + 1][1] = r4[3];
            }

            #pragma unroll
            for (int mt = 0; mt < 2; mt++)
                #pragma unroll
                for (int nt = 0; nt < 8; nt++)
                    mma16816h(acc[mt][nt], aF[mt], bF[nt]);
        }
        __syncthreads();
    }

    // Epilogue: bias, (Q) scale, fp16 pack, [b,h,s,d]
    __half* dst = (z == 0) ? g_Q16 : (z == 1) ? g_K16 : g_V16;
    const float osc = (z == 0) ? 0.125f : 1.0f;
    const int rq = lane >> 2;
    const int cq = (lane & 3) * 2;
    #pragma unroll
    for (int mt = 0; mt < 2; mt++) {
        #pragma unroll
        for (int half = 0; half < 2; half++) {
            const int m  = m0 + wm + mt * 16 + rq + half * 8;
            const int bb = m >> 11;
            const int s  = m & (SEQ - 1);
            #pragma unroll
            for (int nt = 0; nt < 8; nt++) {
                const int nl = wn + nt * 8 + cq;
                const int n  = n0 + nl;
                const int h  = n >> 6, dd = n & 63;
                float vx = (acc[mt][nt][half * 2 + 0] + s_bias[nl])     * osc;
                float vy = (acc[mt][nt][half * 2 + 1] + s_bias[nl + 1]) * osc;
                const size_t idx = (((size_t)(bb * NH + h) * SEQ) + s) * HD + dd;
                *(uint32_t*)(dst + idx) = pack_h2(vx, vy);
            }
        }
    }
}

// ---------------------------------------------------------------------------
// Tensor-core flash attention, fp16.
// CTA = 128 q x (b,h), 8 warps x 16 rows. Key tiles of 64, 3-stage cp.async.
// S: Q x K (1 pass).  PV: (Ph + Pl) x V (2 passes, error-compensated P).
// ---------------------------------------------------------------------------
#define ATILE 9216              // 64 rows * 144B
#define ASTAGE (2 * ATILE)      // K, V
#define NSTAGE 3

__global__ __launch_bounds__(256) void attn_mma_kernel(float* __restrict__ out)
{
    extern __shared__ char ds[];
    const int tid  = threadIdx.x;
    const int w    = tid >> 5;
    const int lane = tid & 31;
    const int gid  = lane >> 2;
    const int tig  = lane & 3;
    const int bh   = blockIdx.y;
    const int q0   = blockIdx.x * 128;

    const size_t base = (size_t)bh * SEQ * HD;
    const uint32_t smb = smem_u32(ds);

    // Q fragments (fp16, pre-scaled), registers for the whole kernel
    uint32_t qh[4][4];
    {
        const __half* Q = g_Q16 + base;
        const int r0 = q0 + w * 16 + gid;
        #pragma unroll
        for (int kt = 0; kt < 4; kt++) {
            const int c0 = kt * 16 + 2 * tig;
            qh[kt][0] = *(const uint32_t*)(Q + (size_t)r0 * HD + c0);
            qh[kt][1] = *(const uint32_t*)(Q + (size_t)(r0 + 8) * HD + c0);
            qh[kt][2] = *(const uint32_t*)(Q + (size_t)r0 * HD + c0 + 8);
            qh[kt][3] = *(const uint32_t*)(Q + (size_t)(r0 + 8) * HD + c0 + 8);
        }
    }

    const __half* tsrc[2] = { g_K16 + base, g_V16 + base };

    auto issue = [&](int c) {
        const uint32_t sb = smb + (c % NSTAGE) * ASTAGE;
        const int k0 = c * 64;
        #pragma unroll
        for (int i = 0; i < 4; i++) {
            const int ch = tid + i * 256;
            const int t2 = ch >> 9, row = (ch >> 3) & 63, seg = (ch & 7) * 16;
            CP_ASYNC16(sb + t2 * ATILE + row * 144 + seg,
                       (const void*)((const char*)(tsrc[t2] + (size_t)(k0 + row) * HD) + seg));
        }
        CP_COMMIT();
    };

    float m_r[2] = { -1e30f, -1e30f };
    float l_r[2] = { 0.f, 0.f };
    float oacc[8][4];
    #pragma unroll
    for (int j = 0; j < 8; j++)
        #pragma unroll
        for (int e = 0; e < 4; e++) oacc[j][e] = 0.f;

    const int b_row = lane & 7;
    const int b_kb  = ((lane >> 3) & 1) * 16;
    const int b_nx  = (lane & 16) ? 8 : 0;
    const int v_row = lane & 15;
    const int v_cb  = (lane & 16) ? 16 : 0;

    issue(0);
    issue(1);

    for (int c = 0; c < 32; c++) {
        if (c + 1 < 32) { CP_WAIT(1); } else { CP_WAIT(0); }
        __syncthreads();
        if (c + 2 < 32) issue(c + 2);   // buffer (c+2)%3 was drained before this sync

        const uint32_t Kb = smb + (c % NSTAGE) * ASTAGE;
        const uint32_t Vb = Kb + ATILE;

        // ---- S = Q K^T (1 pass) ----
        float sacc[8][4];
        #pragma unroll
        for (int j = 0; j < 8; j++)
            #pragma unroll
            for (int e = 0; e < 4; e++) sacc[j][e] = 0.f;

        #pragma unroll
        for (int kt = 0; kt < 4; kt++) {
            const int kb = kt * 32;
            uint32_t bK[4][4];
            #pragma unroll
            for (int p = 0; p < 4; p++)
                ldsm_x4(bK[p], Kb + (p * 16 + b_nx + b_row) * 144 + kb + b_kb);
            #pragma unroll
            for (int j = 0; j < 8; j++)
                mma16816h(sacc[j], qh[kt], &bK[j >> 1][(j & 1) * 2]);
        }

        // ---- online softmax ----
        float mx0 = -1e30f, mx1 = -1e30f;
        #pragma unroll
        for (int j = 0; j < 8; j++) {
            mx0 = fmaxf(mx0, fmaxf(sacc[j][0], sacc[j][1]));
            mx1 = fmaxf(mx1, fmaxf(sacc[j][2], sacc[j][3]));
        }
        mx0 = fmaxf(mx0, __shfl_xor_sync(0xffffffffu, mx0, 1));
        mx0 = fmaxf(mx0, __shfl_xor_sync(0xffffffffu, mx0, 2));
        mx1 = fmaxf(mx1, __shfl_xor_sync(0xffffffffu, mx1, 1));
        mx1 = fmaxf(mx1, __shfl_xor_sync(0xffffffffu, mx1, 2));

        const float mn0 = fmaxf(m_r[0], mx0);
        const float mn1 = fmaxf(m_r[1], mx1);
        const float al0 = __expf(m_r[0] - mn0);
        const float al1 = __expf(m_r[1] - mn1);
        m_r[0] = mn0; m_r[1] = mn1;

        uint32_t pa_h[4][4], pa_l[4][4];
        float rs0 = 0.f, rs1 = 0.f;
        #pragma unroll
        for (int j = 0; j < 8; j++) {
            float p0 = __expf(sacc[j][0] - mn0);
            float p1 = __expf(sacc[j][1] - mn0);
            float p2 = __expf(sacc[j][2] - mn1);
            float p3 = __expf(sacc[j][3] - mn1);
            rs0 += p0 + p1; rs1 += p2 + p3;
            const int kt2 = j >> 1, rb = (j & 1) * 2;
            __half h0 = __float2half_rn(p0), h1 = __float2half_rn(p1);
            __half h2 = __float2half_rn(p2), h3 = __float2half_rn(p3);
            pa_h[kt2][rb + 0] = pack_h2(__half2float(h0), __half2float(h1));
            pa_h[kt2][rb + 1] = pack_h2(__half2float(h2), __half2float(h3));
            pa_l[kt2][rb + 0] = pack_h2(p0 - __half2float(h0), p1 - __half2float(h1));
            pa_l[kt2][rb + 1] = pack_h2(p2 - __half2float(h2), p3 - __half2float(h3));
        }
        rs0 += __shfl_xor_sync(0xffffffffu, rs0, 1);
        rs0 += __shfl_xor_sync(0xffffffffu, rs0, 2);
        rs1 += __shfl_xor_sync(0xffffffffu, rs1, 1);
        rs1 += __shfl_xor_sync(0xffffffffu, rs1, 2);
        l_r[0] = l_r[0] * al0 + rs0;
        l_r[1] = l_r[1] * al1 + rs1;

        #pragma unroll
        for (int j = 0; j < 8; j++) {
            oacc[j][0] *= al0; oacc[j][1] *= al0;
            oacc[j][2] *= al1; oacc[j][3] *= al1;
        }

        // ---- O += P V (2-pass) ----
        #pragma unroll
        for (int kt2 = 0; kt2 < 4; kt2++) {
            uint32_t bV[4][4];
            #pragma unroll
            for (int p = 0; p < 4; p++)
                ldsm_x4_t(bV[p], Vb + (kt2 * 16 + v_row) * 144 + p * 32 + v_cb);
            #pragma unroll
            for (int j = 0; j < 8; j++) {
                const uint32_t* pv = &bV[j >> 1][(j & 1) * 2];
                mma16816h(oacc[j], pa_h[kt2], pv);
                mma16816h(oacc[j], pa_l[kt2], pv);
            }
        }
        __syncthreads();
    }

    // ---- epilogue ----
    const int bb = bh >> 4;
    const int h  = bh & 15;
    const float inv0 = 1.f / l_r[0];
    const float inv1 = 1.f / l_r[1];
    const int qr = q0 + w * 16 + gid;
    #pragma unroll
    for (int j = 0; j < 8; j++) {
        const int dd = 8 * j + 2 * tig;
        float2 v0 = make_float2(oacc[j][0] * inv0, oacc[j][1] * inv0);
        float2 v1 = make_float2(oacc[j][2] * inv1, oacc[j][3] * inv1);
        *(float2*)&out[((size_t)(bb * SEQ + qr)) * EMS + h * HD + dd]     = v0;
        *(float2*)&out[((size_t)(bb * SEQ + qr + 8)) * EMS + h * HD + dd] = v1;
    }
}

// ---------------------------------------------------------------------------
extern "C" void kernel_launch(void* const* d_in, const int* in_sizes, int n_in,
                              void* d_out, int out_size)
{
    const float* embed = (const float*)d_in[0];
    const float* q     = (const float*)d_in[1];
    const float* Wk    = (const float*)d_in[2];
    const float* bk    = (const float*)d_in[3];
    const float* Wq    = (const float*)d_in[4];
    const float* bq    = (const float*)d_in[5];
    const float* Wv    = (const float*)d_in[6];
    const float* bv    = (const float*)d_in[7];
    float* out = (float*)d_out;

    convert_kernel<<<dim3(4096, 5), 256>>>(embed, q, Wq, Wk, Wv);

    cudaFuncSetAttribute(proj_mma_kernel, cudaFuncAttributeMaxDynamicSharedMemorySize, 2 * BUF_B);
    proj_mma_kernel<<<dim3(EMS / 128, (BATCH * SEQ) / 128, 3), 256, 2 * BUF_B>>>(bq, bk, bv);

    cudaFuncSetAttribute(attn_mma_kernel, cudaFuncAttributeMaxDynamicSharedMemorySize, NSTAGE * ASTAGE);
    attn_mma_kernel<<<dim3(SEQ / 128, BATCH * NH), 256, NSTAGE * ASTAGE>>>(out);
}

// round 8
// speedup vs baseline: 7.0916x; 1.1779x over previous
#include <cuda_runtime.h>
#include <cuda_fp16.h>
#include <cstdint>

#define EMS 1024
#define NH 16
#define HD 64
#define SEQ 2048
#define BATCH 2

// ---------------------------------------------------------------------------
// PTX helpers
// ---------------------------------------------------------------------------
__device__ __forceinline__ uint32_t smem_u32(const void* p) {
    uint32_t a;
    asm("{ .reg .u64 t; cvta.to.shared.u64 t, %1; cvt.u32.u64 %0, t; }" : "=r"(a) : "l"(p));
    return a;
}
#define CP_ASYNC16(dst, src) \
    asm volatile("cp.async.cg.shared.global [%0], [%1], 16;" :: "r"(dst), "l"(src) : "memory")
#define CP_COMMIT() asm volatile("cp.async.commit_group;" ::: "memory")
#define CP_WAIT(n)  asm volatile("cp.async.wait_group %0;" :: "n"(n) : "memory")

__device__ __forceinline__ void ldsm_x4(uint32_t* r, uint32_t addr) {
    asm volatile("ldmatrix.sync.aligned.m8n8.x4.shared.b16 {%0,%1,%2,%3}, [%4];"
        : "=r"(r[0]), "=r"(r[1]), "=r"(r[2]), "=r"(r[3]) : "r"(addr));
}
__device__ __forceinline__ void ldsm_x4_t(uint32_t* r, uint32_t addr) {
    asm volatile("ldmatrix.sync.aligned.m8n8.x4.trans.shared.b16 {%0,%1,%2,%3}, [%4];"
        : "=r"(r[0]), "=r"(r[1]), "=r"(r[2]), "=r"(r[3]) : "r"(addr));
}
__device__ __forceinline__ void mma16816h(float* c, const uint32_t* a, const uint32_t* b) {
    asm volatile("mma.sync.aligned.m16n8k16.row.col.f32.f16.f16.f32 "
        "{%0,%1,%2,%3}, {%4,%5,%6,%7}, {%8,%9}, {%0,%1,%2,%3};"
        : "+f"(c[0]), "+f"(c[1]), "+f"(c[2]), "+f"(c[3])
        : "r"(a[0]), "r"(a[1]), "r"(a[2]), "r"(a[3]), "r"(b[0]), "r"(b[1]));
}
__device__ __forceinline__ uint32_t pack_h2(float lo, float hi) {
    __half2 t = __floats2half2_rn(lo, hi);
    return *(uint32_t*)&t;
}

// ---------------------------------------------------------------------------
// Device scratch (fp16)
// ---------------------------------------------------------------------------
__device__ __half g_Q16[BATCH*NH*SEQ*HD];   // pre-scaled by 0.125
__device__ __half g_K16[BATCH*NH*SEQ*HD];
__device__ __half g_V16[BATCH*NH*SEQ*HD];
__device__ __half g_E16[4096 * 1024];
__device__ __half g_X16[4096 * 1024];
__device__ __half g_Wq16[1024 * 1024], g_Wk16[1024 * 1024], g_Wv16[1024 * 1024];

// ---------------------------------------------------------------------------
// fp32 -> fp16 convert
// ---------------------------------------------------------------------------
__global__ __launch_bounds__(256) void convert_kernel(
    const float* __restrict__ embed, const float* __restrict__ qin,
    const float* __restrict__ Wq, const float* __restrict__ Wk, const float* __restrict__ Wv)
{
    const int z = blockIdx.y;
    const float* src; __half* dst; int n4;
    switch (z) {
        case 0: src = embed; dst = g_E16;  n4 = 4096 * 256; break;
        case 1: src = qin;   dst = g_X16;  n4 = 4096 * 256; break;
        case 2: src = Wq;    dst = g_Wq16; n4 = 1024 * 256; break;
        case 3: src = Wk;    dst = g_Wk16; n4 = 1024 * 256; break;
        default: src = Wv;   dst = g_Wv16; n4 = 1024 * 256; break;
    }
    const int t = blockIdx.x * 256 + threadIdx.x;
    if (t >= n4) return;
    float4 v = ((const float4*)src)[t];
    *(uint2*)(dst + (size_t)t * 4) = make_uint2(pack_h2(v.x, v.y), pack_h2(v.z, v.w));
}

// ---------------------------------------------------------------------------
// fp16 1-pass projection: C = A @ W^T + bias. 128x128 CTA tile, 8 warps 4x2.
// 3-stage cp.async pipeline (wait(1) -> sync -> issue(c+2)).
// ---------------------------------------------------------------------------
#define TILE_B 18432            // 128 rows * 144 B
#define BUF_B  (2 * TILE_B)     // A, W
#define PSTAGE 3

__global__ __launch_bounds__(256, 2) void proj_mma_kernel(
    const float* __restrict__ bq, const float* __restrict__ bk, const float* __restrict__ bv)
{
    extern __shared__ char ds[];
    __shared__ float s_bias[128];

    const int tid  = threadIdx.x;
    const int wid  = tid >> 5;
    const int lane = tid & 31;
    const int z  = blockIdx.z;
    const int n0 = blockIdx.x * 128;
    const int m0 = blockIdx.y * 128;

    const __half *A, *W; const float* bias;
    if (z == 0)      { A = g_X16; W = g_Wq16; bias = bq; }
    else if (z == 1) { A = g_E16; W = g_Wk16; bias = bk; }
    else             { A = g_E16; W = g_Wv16; bias = bv; }

    if (tid < 128) s_bias[tid] = bias[n0 + tid];

    const uint32_t smb = smem_u32(ds);
    const __half* srcs[2] = { A + (size_t)m0 * 1024, W + (size_t)n0 * 1024 };

    const int cprow = tid >> 3;
    const int cpseg = (tid & 7) * 16;

    auto issue = [&](int c) {
        const uint32_t bbase = smb + (c % PSTAGE) * BUF_B;
        const int k0 = c * 64;
        #pragma unroll
        for (int t2 = 0; t2 < 2; t2++) {
            const __half* sp = srcs[t2] + k0;
            const uint32_t tbase = bbase + t2 * TILE_B;
            #pragma unroll
            for (int it = 0; it < 4; it++) {
                const int r = cprow + it * 32;
                CP_ASYNC16(tbase + r * 144 + cpseg,
                           (const void*)((const char*)(sp + (size_t)r * 1024) + cpseg));
            }
        }
        CP_COMMIT();
    };

    const int wm = (wid >> 1) * 32;
    const int wn = (wid & 1) * 64;

    float acc[2][8][4];
    #pragma unroll
    for (int mt = 0; mt < 2; mt++)
        #pragma unroll
        for (int nt = 0; nt < 8; nt++)
            #pragma unroll
            for (int e = 0; e < 4; e++) acc[mt][nt][e] = 0.f;

    const int a_row = lane & 15;
    const int a_kb  = ((lane >> 4) << 3) * 2;
    const int b_row = lane & 7;
    const int b_kb  = (((lane >> 3) & 1) << 3) * 2;
    const int b_nx  = (lane >= 16) ? 8 : 0;

    issue(0);
    issue(1);

    for (int c = 0; c < 16; c++) {
        if (c + 1 < 16) { CP_WAIT(1); } else { CP_WAIT(0); }
        __syncthreads();
        if (c + 2 < 16) issue(c + 2);   // buffer (c+2)%3 last read at iter c-1

        const uint32_t bbase = smb + (c % PSTAGE) * BUF_B;
        const uint32_t Abase = bbase;
        const uint32_t Wbase = bbase + TILE_B;

        #pragma unroll
        for (int ks = 0; ks < 4; ks++) {
            const int kb = ks * 32;
            uint32_t aF[2][4];
            #pragma unroll
            for (int mt = 0; mt < 2; mt++)
                ldsm_x4(aF[mt], Abase + (wm + mt * 16 + a_row) * 144 + kb + a_kb);

            uint32_t bF[8][2];
            #pragma unroll
            for (int p = 0; p < 4; p++) {
                uint32_t r4[4];
                ldsm_x4(r4, Wbase + (wn + p * 16 + b_nx + b_row) * 144 + kb + b_kb);
                bF[2 * p][0] = r4[0];     bF[2 * p][1] = r4[1];
                bF[2 * p + 1][0] = r4[2]; bF[2 * p + 1][1] = r4[3];
            }

            #pragma unroll
            for (int mt = 0; mt < 2; mt++)
                #pragma unroll
                for (int nt = 0; nt < 8; nt++)
                    mma16816h(acc[mt][nt], aF[mt], bF[nt]);
        }
        __syncthreads();
    }

    // Epilogue: bias, (Q) scale, fp16 pack, [b,h,s,d]
    __half* dst = (z == 0) ? g_Q16 : (z == 1) ? g_K16 : g_V16;
    const float osc = (z == 0) ? 0.125f : 1.0f;
    const int rq = lane >> 2;
    const int cq = (lane & 3) * 2;
    #pragma unroll
    for (int mt = 0; mt < 2; mt++) {
        #pragma unroll
        for (int half = 0; half < 2; half++) {
            const int m  = m0 + wm + mt * 16 + rq + half * 8;
            const int bb = m >> 11;
            const int s  = m & (SEQ - 1);
            #pragma unroll
            for (int nt = 0; nt < 8; nt++) {
                const int nl = wn + nt * 8 + cq;
                const int n  = n0 + nl;
                const int h  = n >> 6, dd = n & 63;
                float vx = (acc[mt][nt][half * 2 + 0] + s_bias[nl])     * osc;
                float vy = (acc[mt][nt][half * 2 + 1] + s_bias[nl + 1]) * osc;
                const size_t idx = (((size_t)(bb * NH + h) * SEQ) + s) * HD + dd;
                *(uint32_t*)(dst + idx) = pack_h2(vx, vy);
            }
        }
    }
}

// ---------------------------------------------------------------------------
// Tensor-core flash attention, fp16.
// CTA = 128 q x (b,h), 8 warps x 16 rows. Key tiles of 64, 4-stage cp.async.
// S: Q x K (1 pass).  PV: P x V (1 pass).
// ---------------------------------------------------------------------------
#define ATILE 9216              // 64 rows * 144B
#define ASTAGE (2 * ATILE)      // K, V
#define NSTAGE 4

__global__ __launch_bounds__(256) void attn_mma_kernel(float* __restrict__ out)
{
    extern __shared__ char ds[];
    const int tid  = threadIdx.x;
    const int w    = tid >> 5;
    const int lane = tid & 31;
    const int gid  = lane >> 2;
    const int tig  = lane & 3;
    const int bh   = blockIdx.y;
    const int q0   = blockIdx.x * 128;

    const size_t base = (size_t)bh * SEQ * HD;
    const uint32_t smb = smem_u32(ds);

    // Q fragments (fp16, pre-scaled), registers for the whole kernel
    uint32_t qh[4][4];
    {
        const __half* Q = g_Q16 + base;
        const int r0 = q0 + w * 16 + gid;
        #pragma unroll
        for (int kt = 0; kt < 4; kt++) {
            const int c0 = kt * 16 + 2 * tig;
            qh[kt][0] = *(const uint32_t*)(Q + (size_t)r0 * HD + c0);
            qh[kt][1] = *(const uint32_t*)(Q + (size_t)(r0 + 8) * HD + c0);
            qh[kt][2] = *(const uint32_t*)(Q + (size_t)r0 * HD + c0 + 8);
            qh[kt][3] = *(const uint32_t*)(Q + (size_t)(r0 + 8) * HD + c0 + 8);
        }
    }

    const __half* tsrc[2] = { g_K16 + base, g_V16 + base };

    auto issue = [&](int c) {
        const uint32_t sb = smb + (c % NSTAGE) * ASTAGE;
        const int k0 = c * 64;
        #pragma unroll
        for (int i = 0; i < 4; i++) {
            const int ch = tid + i * 256;
            const int t2 = ch >> 9, row = (ch >> 3) & 63, seg = (ch & 7) * 16;
            CP_ASYNC16(sb + t2 * ATILE + row * 144 + seg,
                       (const void*)((const char*)(tsrc[t2] + (size_t)(k0 + row) * HD) + seg));
        }
        CP_COMMIT();
    };

    float m_r[2] = { -1e30f, -1e30f };
    float l_r[2] = { 0.f, 0.f };
    float oacc[8][4];
    #pragma unroll
    for (int j = 0; j < 8; j++)
        #pragma unroll
        for (int e = 0; e < 4; e++) oacc[j][e] = 0.f;

    const int b_row = lane & 7;
    const int b_kb  = ((lane >> 3) & 1) * 16;
    const int b_nx  = (lane & 16) ? 8 : 0;
    const int v_row = lane & 15;
    const int v_cb  = (lane & 16) ? 16 : 0;

    issue(0);
    issue(1);
    issue(2);

    for (int c = 0; c < 32; c++) {
        if (c + 1 < 32) { CP_WAIT(2); } else { CP_WAIT(0); }
        __syncthreads();
        if (c + 3 < 32) issue(c + 3);   // buffer (c+3)%4 last read at iter c-1

        const uint32_t Kb = smb + (c % NSTAGE) * ASTAGE;
        const uint32_t Vb = Kb + ATILE;

        // ---- S = Q K^T (1 pass) ----
        float sacc[8][4];
        #pragma unroll
        for (int j = 0; j < 8; j++)
            #pragma unroll
            for (int e = 0; e < 4; e++) sacc[j][e] = 0.f;

        #pragma unroll
        for (int kt = 0; kt < 4; kt++) {
            const int kb = kt * 32;
            uint32_t bK[4][4];
            #pragma unroll
            for (int p = 0; p < 4; p++)
                ldsm_x4(bK[p], Kb + (p * 16 + b_nx + b_row) * 144 + kb + b_kb);
            #pragma unroll
            for (int j = 0; j < 8; j++)
                mma16816h(sacc[j], qh[kt], &bK[j >> 1][(j & 1) * 2]);
        }

        // ---- online softmax ----
        float mx0 = -1e30f, mx1 = -1e30f;
        #pragma unroll
        for (int j = 0; j < 8; j++) {
            mx0 = fmaxf(mx0, fmaxf(sacc[j][0], sacc[j][1]));
            mx1 = fmaxf(mx1, fmaxf(sacc[j][2], sacc[j][3]));
        }
        mx0 = fmaxf(mx0, __shfl_xor_sync(0xffffffffu, mx0, 1));
        mx0 = fmaxf(mx0, __shfl_xor_sync(0xffffffffu, mx0, 2));
        mx1 = fmaxf(mx1, __shfl_xor_sync(0xffffffffu, mx1, 1));
        mx1 = fmaxf(mx1, __shfl_xor_sync(0xffffffffu, mx1, 2));

        const float mn0 = fmaxf(m_r[0], mx0);
        const float mn1 = fmaxf(m_r[1], mx1);
        const float al0 = __expf(m_r[0] - mn0);
        const float al1 = __expf(m_r[1] - mn1);
        m_r[0] = mn0; m_r[1] = mn1;

        uint32_t pa_h[4][4];
        float rs0 = 0.f, rs1 = 0.f;
        #pragma unroll
        for (int j = 0; j < 8; j++) {
            float p0 = __expf(sacc[j][0] - mn0);
            float p1 = __expf(sacc[j][1] - mn0);
            float p2 = __expf(sacc[j][2] - mn1);
            float p3 = __expf(sacc[j][3] - mn1);
            rs0 += p0 + p1; rs1 += p2 + p3;
            const int kt2 = j >> 1, rb = (j & 1) * 2;
            pa_h[kt2][rb + 0] = pack_h2(p0, p1);
            pa_h[kt2][rb + 1] = pack_h2(p2, p3);
        }
        rs0 += __shfl_xor_sync(0xffffffffu, rs0, 1);
        rs0 += __shfl_xor_sync(0xffffffffu, rs0, 2);
        rs1 += __shfl_xor_sync(0xffffffffu, rs1, 1);
        rs1 += __shfl_xor_sync(0xffffffffu, rs1, 2);
        l_r[0] = l_r[0] * al0 + rs0;
        l_r[1] = l_r[1] * al1 + rs1;

        #pragma unroll
        for (int j = 0; j < 8; j++) {
            oacc[j][0] *= al0; oacc[j][1] *= al0;
            oacc[j][2] *= al1; oacc[j][3] *= al1;
        }

        // ---- O += P V (1 pass) ----
        #pragma unroll
        for (int kt2 = 0; kt2 < 4; kt2++) {
            uint32_t bV[4][4];
            #pragma unroll
            for (int p = 0; p < 4; p++)
                ldsm_x4_t(bV[p], Vb + (kt2 * 16 + v_row) * 144 + p * 32 + v_cb);
            #pragma unroll
            for (int j = 0; j < 8; j++)
                mma16816h(oacc[j], pa_h[kt2], &bV[j >> 1][(j & 1) * 2]);
        }
        __syncthreads();
    }

    // ---- epilogue ----
    const int bb = bh >> 4;
    const int h  = bh & 15;
    const float inv0 = 1.f / l_r[0];
    const float inv1 = 1.f / l_r[1];
    const int qr = q0 + w * 16 + gid;
    #pragma unroll
    for (int j = 0; j < 8; j++) {
        const int dd = 8 * j + 2 * tig;
        float2 v0 = make_float2(oacc[j][0] * inv0, oacc[j][1] * inv0);
        float2 v1 = make_float2(oacc[j][2] * inv1, oacc[j][3] * inv1);
        *(float2*)&out[((size_t)(bb * SEQ + qr)) * EMS + h * HD + dd]     = v0;
        *(float2*)&out[((size_t)(bb * SEQ + qr + 8)) * EMS + h * HD + dd] = v1;
    }
}

// ---------------------------------------------------------------------------
extern "C" void kernel_launch(void* const* d_in, const int* in_sizes, int n_in,
                              void* d_out, int out_size)
{
    const float* embed = (const float*)d_in[0];
    const float* q     = (const float*)d_in[1];
    const float* Wk    = (const float*)d_in[2];
    const float* bk    = (const float*)d_in[3];
    const float* Wq    = (const float*)d_in[4];
    const float* bq    = (const float*)d_in[5];
    const float* Wv    = (const float*)d_in[6];
    const float* bv    = (const float*)d_in[7];
    float* out = (float*)d_out;

    convert_kernel<<<dim3(4096, 5), 256>>>(embed, q, Wq, Wk, Wv);

    cudaFuncSetAttribute(proj_mma_kernel, cudaFuncAttributeMaxDynamicSharedMemorySize, PSTAGE * BUF_B);
    proj_mma_kernel<<<dim3(EMS / 128, (BATCH * SEQ) / 128, 3), 256, PSTAGE * BUF_B>>>(bq, bk, bv);

    cudaFuncSetAttribute(attn_mma_kernel, cudaFuncAttributeMaxDynamicSharedMemorySize, NSTAGE * ASTAGE);
    attn_mma_kernel<<<dim3(SEQ / 128, BATCH * NH), 256, NSTAGE * ASTAGE>>>(out);
}

// round 9
// speedup vs baseline: 7.2863x; 1.0275x over previous
#include <cuda_runtime.h>
#include <cuda_fp16.h>
#include <cstdint>

#define EMS 1024
#define NH 16
#define HD 64
#define SEQ 2048
#define BATCH 2

// ---------------------------------------------------------------------------
// PTX helpers
// ---------------------------------------------------------------------------
__device__ __forceinline__ uint32_t smem_u32(const void* p) {
    uint32_t a;
    asm("{ .reg .u64 t; cvta.to.shared.u64 t, %1; cvt.u32.u64 %0, t; }" : "=r"(a) : "l"(p));
    return a;
}
#define CP_ASYNC16(dst, src) \
    asm volatile("cp.async.cg.shared.global [%0], [%1], 16;" :: "r"(dst), "l"(src) : "memory")
#define CP_COMMIT() asm volatile("cp.async.commit_group;" ::: "memory")
#define CP_WAIT(n)  asm volatile("cp.async.wait_group %0;" :: "n"(n) : "memory")

__device__ __forceinline__ void ldsm_x4(uint32_t* r, uint32_t addr) {
    asm volatile("ldmatrix.sync.aligned.m8n8.x4.shared.b16 {%0,%1,%2,%3}, [%4];"
        : "=r"(r[0]), "=r"(r[1]), "=r"(r[2]), "=r"(r[3]) : "r"(addr));
}
__device__ __forceinline__ void ldsm_x4_t(uint32_t* r, uint32_t addr) {
    asm volatile("ldmatrix.sync.aligned.m8n8.x4.trans.shared.b16 {%0,%1,%2,%3}, [%4];"
        : "=r"(r[0]), "=r"(r[1]), "=r"(r[2]), "=r"(r[3]) : "r"(addr));
}
__device__ __forceinline__ void mma16816h(float* c, const uint32_t* a, const uint32_t* b) {
    asm volatile("mma.sync.aligned.m16n8k16.row.col.f32.f16.f16.f32 "
        "{%0,%1,%2,%3}, {%4,%5,%6,%7}, {%8,%9}, {%0,%1,%2,%3};"
        : "+f"(c[0]), "+f"(c[1]), "+f"(c[2]), "+f"(c[3])
        : "r"(a[0]), "r"(a[1]), "r"(a[2]), "r"(a[3]), "r"(b[0]), "r"(b[1]));
}
__device__ __forceinline__ uint32_t pack_h2(float lo, float hi) {
    __half2 t = __floats2half2_rn(lo, hi);
    return *(uint32_t*)&t;
}

// ---------------------------------------------------------------------------
// Device scratch (fp16)
// ---------------------------------------------------------------------------
__device__ __half g_Q16[BATCH*NH*SEQ*HD];   // pre-scaled by 0.125
__device__ __half g_K16[BATCH*NH*SEQ*HD];
__device__ __half g_V16[BATCH*NH*SEQ*HD];
__device__ __half g_E16[4096 * 1024];
__device__ __half g_X16[4096 * 1024];
__device__ __half g_Wq16[1024 * 1024], g_Wk16[1024 * 1024], g_Wv16[1024 * 1024];

// ---------------------------------------------------------------------------
// fp32 -> fp16 convert
// ---------------------------------------------------------------------------
__global__ __launch_bounds__(256) void convert_kernel(
    const float* __restrict__ embed, const float* __restrict__ qin,
    const float* __restrict__ Wq, const float* __restrict__ Wk, const float* __restrict__ Wv)
{
    const int z = blockIdx.y;
    const float* src; __half* dst; int n4;
    switch (z) {
        case 0: src = embed; dst = g_E16;  n4 = 4096 * 256; break;
        case 1: src = qin;   dst = g_X16;  n4 = 4096 * 256; break;
        case 2: src = Wq;    dst = g_Wq16; n4 = 1024 * 256; break;
        case 3: src = Wk;    dst = g_Wk16; n4 = 1024 * 256; break;
        default: src = Wv;   dst = g_Wv16; n4 = 1024 * 256; break;
    }
    const int t = blockIdx.x * 256 + threadIdx.x;
    if (t >= n4) return;
    float4 v = ((const float4*)src)[t];
    *(uint2*)(dst + (size_t)t * 4) = make_uint2(pack_h2(v.x, v.y), pack_h2(v.z, v.w));
}

// ---------------------------------------------------------------------------
// fp16 1-pass projection: C = A @ W^T + bias. 128x128 CTA tile, 8 warps 4x2.
// 3-stage cp.async pipeline.
// ---------------------------------------------------------------------------
#define TILE_B 18432            // 128 rows * 144 B
#define BUF_B  (2 * TILE_B)     // A, W
#define PSTAGE 3

__global__ __launch_bounds__(256, 2) void proj_mma_kernel(
    const float* __restrict__ bq, const float* __restrict__ bk, const float* __restrict__ bv)
{
    extern __shared__ char ds[];
    __shared__ float s_bias[128];

    const int tid  = threadIdx.x;
    const int wid  = tid >> 5;
    const int lane = tid & 31;
    const int z  = blockIdx.z;
    const int n0 = blockIdx.x * 128;
    const int m0 = blockIdx.y * 128;

    const __half *A, *W; const float* bias;
    if (z == 0)      { A = g_X16; W = g_Wq16; bias = bq; }
    else if (z == 1) { A = g_E16; W = g_Wk16; bias = bk; }
    else             { A = g_E16; W = g_Wv16; bias = bv; }

    if (tid < 128) s_bias[tid] = bias[n0 + tid];

    const uint32_t smb = smem_u32(ds);
    const __half* srcs[2] = { A + (size_t)m0 * 1024, W + (size_t)n0 * 1024 };

    const int cprow = tid >> 3;
    const int cpseg = (tid & 7) * 16;

    auto issue = [&](int c) {
        const uint32_t bbase = smb + (c % PSTAGE) * BUF_B;
        const int k0 = c * 64;
        #pragma unroll
        for (int t2 = 0; t2 < 2; t2++) {
            const __half* sp = srcs[t2] + k0;
            const uint32_t tbase = bbase + t2 * TILE_B;
            #pragma unroll
            for (int it = 0; it < 4; it++) {
                const int r = cprow + it * 32;
                CP_ASYNC16(tbase + r * 144 + cpseg,
                           (const void*)((const char*)(sp + (size_t)r * 1024) + cpseg));
            }
        }
        CP_COMMIT();
    };

    const int wm = (wid >> 1) * 32;
    const int wn = (wid & 1) * 64;

    float acc[2][8][4];
    #pragma unroll
    for (int mt = 0; mt < 2; mt++)
        #pragma unroll
        for (int nt = 0; nt < 8; nt++)
            #pragma unroll
            for (int e = 0; e < 4; e++) acc[mt][nt][e] = 0.f;

    const int a_row = lane & 15;
    const int a_kb  = ((lane >> 4) << 3) * 2;
    const int b_row = lane & 7;
    const int b_kb  = (((lane >> 3) & 1) << 3) * 2;
    const int b_nx  = (lane >= 16) ? 8 : 0;

    issue(0);
    issue(1);

    for (int c = 0; c < 16; c++) {
        if (c + 1 < 16) { CP_WAIT(1); } else { CP_WAIT(0); }
        __syncthreads();
        if (c + 2 < 16) issue(c + 2);

        const uint32_t bbase = smb + (c % PSTAGE) * BUF_B;
        const uint32_t Abase = bbase;
        const uint32_t Wbase = bbase + TILE_B;

        #pragma unroll
        for (int ks = 0; ks < 4; ks++) {
            const int kb = ks * 32;
            uint32_t aF[2][4];
            #pragma unroll
            for (int mt = 0; mt < 2; mt++)
                ldsm_x4(aF[mt], Abase + (wm + mt * 16 + a_row) * 144 + kb + a_kb);

            uint32_t bF[8][2];
            #pragma unroll
            for (int p = 0; p < 4; p++) {
                uint32_t r4[4];
                ldsm_x4(r4, Wbase + (wn + p * 16 + b_nx + b_row) * 144 + kb + b_kb);
                bF[2 * p][0] = r4[0];     bF[2 * p][1] = r4[1];
                bF[2 * p + 1][0] = r4[2]; bF[2 * p + 1][1] = r4[3];
            }

            #pragma unroll
            for (int mt = 0; mt < 2; mt++)
                #pragma unroll
                for (int nt = 0; nt < 8; nt++)
                    mma16816h(acc[mt][nt], aF[mt], bF[nt]);
        }
        __syncthreads();
    }

    // Epilogue: bias, (Q) scale, fp16 pack, [b,h,s,d]
    __half* dst = (z == 0) ? g_Q16 : (z == 1) ? g_K16 : g_V16;
    const float osc = (z == 0) ? 0.125f : 1.0f;
    const int rq = lane >> 2;
    const int cq = (lane & 3) * 2;
    #pragma unroll
    for (int mt = 0; mt < 2; mt++) {
        #pragma unroll
        for (int half = 0; half < 2; half++) {
            const int m  = m0 + wm + mt * 16 + rq + half * 8;
            const int bb = m >> 11;
            const int s  = m & (SEQ - 1);
            #pragma unroll
            for (int nt = 0; nt < 8; nt++) {
                const int nl = wn + nt * 8 + cq;
                const int n  = n0 + nl;
                const int h  = n >> 6, dd = n & 63;
                float vx = (acc[mt][nt][half * 2 + 0] + s_bias[nl])     * osc;
                float vy = (acc[mt][nt][half * 2 + 1] + s_bias[nl + 1]) * osc;
                const size_t idx = (((size_t)(bb * NH + h) * SEQ) + s) * HD + dd;
                *(uint32_t*)(dst + idx) = pack_h2(vx, vy);
            }
        }
    }
}

// ---------------------------------------------------------------------------
// Tensor-core flash attention, fp16, 32 q-rows PER WARP (256 q per CTA).
// Each bK/bV fragment feeds 2 m-groups -> half the ldsm + softmax overhead
// per MMA vs the 16-row version. 4-stage cp.async, 64-key tiles.
// ---------------------------------------------------------------------------
#define ATILE 9216              // 64 rows * 144B
#define ASTAGE (2 * ATILE)      // K, V
#define NSTAGE 4

__global__ __launch_bounds__(256) void attn_mma_kernel(float* __restrict__ out)
{
    extern __shared__ char ds[];
    const int tid  = threadIdx.x;
    const int w    = tid >> 5;
    const int lane = tid & 31;
    const int gid  = lane >> 2;
    const int tig  = lane & 3;
    const int bh   = blockIdx.y;
    const int q0   = blockIdx.x * 256;

    const size_t base = (size_t)bh * SEQ * HD;
    const uint32_t smb = smem_u32(ds);

    // Q fragments: 2 m-groups of 16 rows each (fp16, pre-scaled)
    uint32_t qh[2][4][4];
    {
        const __half* Q = g_Q16 + base;
        #pragma unroll
        for (int g = 0; g < 2; g++) {
            const int r0 = q0 + w * 32 + g * 16 + gid;
            #pragma unroll
            for (int kt = 0; kt < 4; kt++) {
                const int c0 = kt * 16 + 2 * tig;
                qh[g][kt][0] = *(const uint32_t*)(Q + (size_t)r0 * HD + c0);
                qh[g][kt][1] = *(const uint32_t*)(Q + (size_t)(r0 + 8) * HD + c0);
                qh[g][kt][2] = *(const uint32_t*)(Q + (size_t)r0 * HD + c0 + 8);
                qh[g][kt][3] = *(const uint32_t*)(Q + (size_t)(r0 + 8) * HD + c0 + 8);
            }
        }
    }

    const __half* tsrc[2] = { g_K16 + base, g_V16 + base };

    auto issue = [&](int c) {
        const uint32_t sb = smb + (c % NSTAGE) * ASTAGE;
        const int k0 = c * 64;
        #pragma unroll
        for (int i = 0; i < 4; i++) {
            const int ch = tid + i * 256;
            const int t2 = ch >> 9, row = (ch >> 3) & 63, seg = (ch & 7) * 16;
            CP_ASYNC16(sb + t2 * ATILE + row * 144 + seg,
                       (const void*)((const char*)(tsrc[t2] + (size_t)(k0 + row) * HD) + seg));
        }
        CP_COMMIT();
    };

    float m_r[2][2], l_r[2][2];
    float oacc[2][8][4];
    #pragma unroll
    for (int g = 0; g < 2; g++) {
        m_r[g][0] = -1e30f; m_r[g][1] = -1e30f;
        l_r[g][0] = 0.f;    l_r[g][1] = 0.f;
        #pragma unroll
        for (int j = 0; j < 8; j++)
            #pragma unroll
            for (int e = 0; e < 4; e++) oacc[g][j][e] = 0.f;
    }

    const int b_row = lane & 7;
    const int b_kb  = ((lane >> 3) & 1) * 16;
    const int b_nx  = (lane & 16) ? 8 : 0;
    const int v_row = lane & 15;
    const int v_cb  = (lane & 16) ? 16 : 0;

    issue(0);
    issue(1);
    issue(2);

    for (int c = 0; c < 32; c++) {
        if (c + 1 < 32) { CP_WAIT(2); } else { CP_WAIT(0); }
        __syncthreads();
        if (c + 3 < 32) issue(c + 3);

        const uint32_t Kb = smb + (c % NSTAGE) * ASTAGE;
        const uint32_t Vb = Kb + ATILE;

        // ---- S = Q K^T (both m-groups share each bK fragment) ----
        float sacc[2][8][4];
        #pragma unroll
        for (int g = 0; g < 2; g++)
            #pragma unroll
            for (int j = 0; j < 8; j++)
                #pragma unroll
                for (int e = 0; e < 4; e++) sacc[g][j][e] = 0.f;

        #pragma unroll
        for (int kt = 0; kt < 4; kt++) {
            const int kb = kt * 32;
            uint32_t bK[4][4];
            #pragma unroll
            for (int p = 0; p < 4; p++)
                ldsm_x4(bK[p], Kb + (p * 16 + b_nx + b_row) * 144 + kb + b_kb);
            #pragma unroll
            for (int j = 0; j < 8; j++) {
                const uint32_t* pk = &bK[j >> 1][(j & 1) * 2];
                mma16816h(sacc[0][j], qh[0][kt], pk);
                mma16816h(sacc[1][j], qh[1][kt], pk);
            }
        }

        // ---- online softmax (per m-group) + P fragments ----
        uint32_t pa[2][4][4];
        #pragma unroll
        for (int g = 0; g < 2; g++) {
            float mx0 = -1e30f, mx1 = -1e30f;
            #pragma unroll
            for (int j = 0; j < 8; j++) {
                mx0 = fmaxf(mx0, fmaxf(sacc[g][j][0], sacc[g][j][1]));
                mx1 = fmaxf(mx1, fmaxf(sacc[g][j][2], sacc[g][j][3]));
            }
            mx0 = fmaxf(mx0, __shfl_xor_sync(0xffffffffu, mx0, 1));
            mx0 = fmaxf(mx0, __shfl_xor_sync(0xffffffffu, mx0, 2));
            mx1 = fmaxf(mx1, __shfl_xor_sync(0xffffffffu, mx1, 1));
            mx1 = fmaxf(mx1, __shfl_xor_sync(0xffffffffu, mx1, 2));

            const float mn0 = fmaxf(m_r[g][0], mx0);
            const float mn1 = fmaxf(m_r[g][1], mx1);
            const float al0 = __expf(m_r[g][0] - mn0);
            const float al1 = __expf(m_r[g][1] - mn1);
            m_r[g][0] = mn0; m_r[g][1] = mn1;

            float rs0 = 0.f, rs1 = 0.f;
            #pragma unroll
            for (int j = 0; j < 8; j++) {
                float p0 = __expf(sacc[g][j][0] - mn0);
                float p1 = __expf(sacc[g][j][1] - mn0);
                float p2 = __expf(sacc[g][j][2] - mn1);
                float p3 = __expf(sacc[g][j][3] - mn1);
                rs0 += p0 + p1; rs1 += p2 + p3;
                const int kt2 = j >> 1, rb = (j & 1) * 2;
                pa[g][kt2][rb + 0] = pack_h2(p0, p1);
                pa[g][kt2][rb + 1] = pack_h2(p2, p3);
            }
            rs0 += __shfl_xor_sync(0xffffffffu, rs0, 1);
            rs0 += __shfl_xor_sync(0xffffffffu, rs0, 2);
            rs1 += __shfl_xor_sync(0xffffffffu, rs1, 1);
            rs1 += __shfl_xor_sync(0xffffffffu, rs1, 2);
            l_r[g][0] = l_r[g][0] * al0 + rs0;
            l_r[g][1] = l_r[g][1] * al1 + rs1;

            #pragma unroll
            for (int j = 0; j < 8; j++) {
                oacc[g][j][0] *= al0; oacc[g][j][1] *= al0;
                oacc[g][j][2] *= al1; oacc[g][j][3] *= al1;
            }
        }

        // ---- O += P V (both m-groups share each bV fragment) ----
        #pragma unroll
        for (int kt2 = 0; kt2 < 4; kt2++) {
            uint32_t bV[4][4];
            #pragma unroll
            for (int p = 0; p < 4; p++)
                ldsm_x4_t(bV[p], Vb + (kt2 * 16 + v_row) * 144 + p * 32 + v_cb);
            #pragma unroll
            for (int j = 0; j < 8; j++) {
                const uint32_t* pv = &bV[j >> 1][(j & 1) * 2];
                mma16816h(oacc[0][j], pa[0][kt2], pv);
                mma16816h(oacc[1][j], pa[1][kt2], pv);
            }
        }
        __syncthreads();
    }

    // ---- epilogue ----
    const int bb = bh >> 4;
    const int h  = bh & 15;
    #pragma unroll
    for (int g = 0; g < 2; g++) {
        const float inv0 = 1.f / l_r[g][0];
        const float inv1 = 1.f / l_r[g][1];
        const int qr = q0 + w * 32 + g * 16 + gid;
        #pragma unroll
        for (int j = 0; j < 8; j++) {
            const int dd = 8 * j + 2 * tig;
            float2 v0 = make_float2(oacc[g][j][0] * inv0, oacc[g][j][1] * inv0);
            float2 v1 = make_float2(oacc[g][j][2] * inv1, oacc[g][j][3] * inv1);
            *(float2*)&out[((size_t)(bb * SEQ + qr)) * EMS + h * HD + dd]     = v0;
            *(float2*)&out[((size_t)(bb * SEQ + qr + 8)) * EMS + h * HD + dd] = v1;
        }
    }
}

// ---------------------------------------------------------------------------
extern "C" void kernel_launch(void* const* d_in, const int* in_sizes, int n_in,
                              void* d_out, int out_size)
{
    const float* embed = (const float*)d_in[0];
    const float* q     = (const float*)d_in[1];
    const float* Wk    = (const float*)d_in[2];
    const float* bk    = (const float*)d_in[3];
    const float* Wq    = (const float*)d_in[4];
    const float* bq    = (const float*)d_in[5];
    const float* Wv    = (const float*)d_in[6];
    const float* bv    = (const float*)d_in[7];
    float* out = (float*)d_out;

    convert_kernel<<<dim3(4096, 5), 256>>>(embed, q, Wq, Wk, Wv);

    cudaFuncSetAttribute(proj_mma_kernel, cudaFuncAttributeMaxDynamicSharedMemorySize, PSTAGE * BUF_B);
    proj_mma_kernel<<<dim3(EMS / 128, (BATCH * SEQ) / 128, 3), 256, PSTAGE * BUF_B>>>(bq, bk, bv);

    cudaFuncSetAttribute(attn_mma_kernel, cudaFuncAttributeMaxDynamicSharedMemorySize, NSTAGE * ASTAGE);
    attn_mma_kernel<<<dim3(SEQ / 256, BATCH * NH), 256, NSTAGE * ASTAGE>>>(out);
}

// round 10
// speedup vs baseline: 7.4006x; 1.0157x over previous
#include <cuda_runtime.h>
#include <cuda_fp16.h>
#include <cstdint>

#define EMS 1024
#define NH 16
#define HD 64
#define SEQ 2048
#define BATCH 2

// ---------------------------------------------------------------------------
// PTX helpers
// ---------------------------------------------------------------------------
__device__ __forceinline__ uint32_t smem_u32(const void* p) {
    uint32_t a;
    asm("{ .reg .u64 t; cvta.to.shared.u64 t, %1; cvt.u32.u64 %0, t; }" : "=r"(a) : "l"(p));
    return a;
}
#define CP_ASYNC16(dst, src) \
    asm volatile("cp.async.cg.shared.global [%0], [%1], 16;" :: "r"(dst), "l"(src) : "memory")
#define CP_COMMIT() asm volatile("cp.async.commit_group;" ::: "memory")
#define CP_WAIT(n)  asm volatile("cp.async.wait_group %0;" :: "n"(n) : "memory")

__device__ __forceinline__ void ldsm_x4(uint32_t* r, uint32_t addr) {
    asm volatile("ldmatrix.sync.aligned.m8n8.x4.shared.b16 {%0,%1,%2,%3}, [%4];"
        : "=r"(r[0]), "=r"(r[1]), "=r"(r[2]), "=r"(r[3]) : "r"(addr));
}
__device__ __forceinline__ void ldsm_x4_t(uint32_t* r, uint32_t addr) {
    asm volatile("ldmatrix.sync.aligned.m8n8.x4.trans.shared.b16 {%0,%1,%2,%3}, [%4];"
        : "=r"(r[0]), "=r"(r[1]), "=r"(r[2]), "=r"(r[3]) : "r"(addr));
}
__device__ __forceinline__ void mma16816h(float* c, const uint32_t* a, const uint32_t* b) {
    asm volatile("mma.sync.aligned.m16n8k16.row.col.f32.f16.f16.f32 "
        "{%0,%1,%2,%3}, {%4,%5,%6,%7}, {%8,%9}, {%0,%1,%2,%3};"
        : "+f"(c[0]), "+f"(c[1]), "+f"(c[2]), "+f"(c[3])
        : "r"(a[0]), "r"(a[1]), "r"(a[2]), "r"(a[3]), "r"(b[0]), "r"(b[1]));
}
__device__ __forceinline__ uint32_t pack_h2(float lo, float hi) {
    __half2 t = __floats2half2_rn(lo, hi);
    return *(uint32_t*)&t;
}

// ---------------------------------------------------------------------------
// Device scratch (fp16)
// ---------------------------------------------------------------------------
__device__ __half g_Q16[BATCH*NH*SEQ*HD];   // pre-scaled by 0.125
__device__ __half g_K16[BATCH*NH*SEQ*HD];
__device__ __half g_V16[BATCH*NH*SEQ*HD];
__device__ __half g_E16[4096 * 1024];
__device__ __half g_X16[4096 * 1024];
__device__ __half g_Wq16[1024 * 1024], g_Wk16[1024 * 1024], g_Wv16[1024 * 1024];

// ---------------------------------------------------------------------------
// fp32 -> fp16 convert
// ---------------------------------------------------------------------------
__global__ __launch_bounds__(256) void convert_kernel(
    const float* __restrict__ embed, const float* __restrict__ qin,
    const float* __restrict__ Wq, const float* __restrict__ Wk, const float* __restrict__ Wv)
{
    const int z = blockIdx.y;
    const float* src; __half* dst; int n4;
    switch (z) {
        case 0: src = embed; dst = g_E16;  n4 = 4096 * 256; break;
        case 1: src = qin;   dst = g_X16;  n4 = 4096 * 256; break;
        case 2: src = Wq;    dst = g_Wq16; n4 = 1024 * 256; break;
        case 3: src = Wk;    dst = g_Wk16; n4 = 1024 * 256; break;
        default: src = Wv;   dst = g_Wv16; n4 = 1024 * 256; break;
    }
    const int t = blockIdx.x * 256 + threadIdx.x;
    if (t >= n4) return;
    float4 v = ((const float4*)src)[t];
    *(uint2*)(dst + (size_t)t * 4) = make_uint2(pack_h2(v.x, v.y), pack_h2(v.z, v.w));
}

// ---------------------------------------------------------------------------
// fp16 1-pass projection: C = A @ W^T + bias. 128x128 CTA tile, 8 warps 4x2.
// 3-stage cp.async pipeline; single sync per iteration.
// ---------------------------------------------------------------------------
#define TILE_B 18432            // 128 rows * 144 B
#define BUF_B  (2 * TILE_B)     // A, W
#define PSTAGE 3

__global__ __launch_bounds__(256, 2) void proj_mma_kernel(
    const float* __restrict__ bq, const float* __restrict__ bk, const float* __restrict__ bv)
{
    extern __shared__ char ds[];
    __shared__ float s_bias[128];

    const int tid  = threadIdx.x;
    const int wid  = tid >> 5;
    const int lane = tid & 31;
    const int z  = blockIdx.z;
    const int n0 = blockIdx.x * 128;
    const int m0 = blockIdx.y * 128;

    const __half *A, *W; const float* bias;
    if (z == 0)      { A = g_X16; W = g_Wq16; bias = bq; }
    else if (z == 1) { A = g_E16; W = g_Wk16; bias = bk; }
    else             { A = g_E16; W = g_Wv16; bias = bv; }

    if (tid < 128) s_bias[tid] = bias[n0 + tid];

    const uint32_t smb = smem_u32(ds);
    const __half* srcs[2] = { A + (size_t)m0 * 1024, W + (size_t)n0 * 1024 };

    const int cprow = tid >> 3;
    const int cpseg = (tid & 7) * 16;

    auto issue = [&](int c) {
        const uint32_t bbase = smb + (c % PSTAGE) * BUF_B;
        const int k0 = c * 64;
        #pragma unroll
        for (int t2 = 0; t2 < 2; t2++) {
            const __half* sp = srcs[t2] + k0;
            const uint32_t tbase = bbase + t2 * TILE_B;
            #pragma unroll
            for (int it = 0; it < 4; it++) {
                const int r = cprow + it * 32;
                CP_ASYNC16(tbase + r * 144 + cpseg,
                           (const void*)((const char*)(sp + (size_t)r * 1024) + cpseg));
            }
        }
        CP_COMMIT();
    };

    const int wm = (wid >> 1) * 32;
    const int wn = (wid & 1) * 64;

    float acc[2][8][4];
    #pragma unroll
    for (int mt = 0; mt < 2; mt++)
        #pragma unroll
        for (int nt = 0; nt < 8; nt++)
            #pragma unroll
            for (int e = 0; e < 4; e++) acc[mt][nt][e] = 0.f;

    const int a_row = lane & 15;
    const int a_kb  = ((lane >> 4) << 3) * 2;
    const int b_row = lane & 7;
    const int b_kb  = (((lane >> 3) & 1) << 3) * 2;
    const int b_nx  = (lane >= 16) ? 8 : 0;

    issue(0);
    issue(1);

    for (int c = 0; c < 16; c++) {
        if (c + 1 < 16) { CP_WAIT(1); } else { CP_WAIT(0); }
        __syncthreads();                 // orders prior-iter reads before overwrite below
        if (c + 2 < 16) issue(c + 2);

        const uint32_t bbase = smb + (c % PSTAGE) * BUF_B;
        const uint32_t Abase = bbase;
        const uint32_t Wbase = bbase + TILE_B;

        #pragma unroll
        for (int ks = 0; ks < 4; ks++) {
            const int kb = ks * 32;
            uint32_t aF[2][4];
            #pragma unroll
            for (int mt = 0; mt < 2; mt++)
                ldsm_x4(aF[mt], Abase + (wm + mt * 16 + a_row) * 144 + kb + a_kb);

            uint32_t bF[8][2];
            #pragma unroll
            for (int p = 0; p < 4; p++) {
                uint32_t r4[4];
                ldsm_x4(r4, Wbase + (wn + p * 16 + b_nx + b_row) * 144 + kb + b_kb);
                bF[2 * p][0] = r4[0];     bF[2 * p][1] = r4[1];
                bF[2 * p + 1][0] = r4[2]; bF[2 * p + 1][1] = r4[3];
            }

            #pragma unroll
            for (int mt = 0; mt < 2; mt++)
                #pragma unroll
                for (int nt = 0; nt < 8; nt++)
                    mma16816h(acc[mt][nt], aF[mt], bF[nt]);
        }
    }

    // Epilogue: bias, (Q) scale, fp16 pack, [b,h,s,d]
    __half* dst = (z == 0) ? g_Q16 : (z == 1) ? g_K16 : g_V16;
    const float osc = (z == 0) ? 0.125f : 1.0f;
    const int rq = lane >> 2;
    const int cq = (lane & 3) * 2;
    #pragma unroll
    for (int mt = 0; mt < 2; mt++) {
        #pragma unroll
        for (int half = 0; half < 2; half++) {
            const int m  = m0 + wm + mt * 16 + rq + half * 8;
            const int bb = m >> 11;
            const int s  = m & (SEQ - 1);
            #pragma unroll
            for (int nt = 0; nt < 8; nt++) {
                const int nl = wn + nt * 8 + cq;
                const int n  = n0 + nl;
                const int h  = n >> 6, dd = n & 63;
                float vx = (acc[mt][nt][half * 2 + 0] + s_bias[nl])     * osc;
                float vy = (acc[mt][nt][half * 2 + 1] + s_bias[nl + 1]) * osc;
                const size_t idx = (((size_t)(bb * NH + h) * SEQ) + s) * HD + dd;
                *(uint32_t*)(dst + idx) = pack_h2(vx, vy);
            }
        }
    }
}

// ---------------------------------------------------------------------------
// Tensor-core flash attention, fp16.
// 4-warp CTAs (128 thr), 16 q-rows/warp -> 64 q per CTA, occupancy 3
// (12 warps/SM = 3/SMSP) to overlap MUFU/ldsm under the HMMA stream.
// 64-key tiles, 3-stage cp.async, one sync per iteration.
// ---------------------------------------------------------------------------
#define ATILE 9216              // 64 rows * 144B
#define ASTAGE (2 * ATILE)      // K, V
#define NSTAGE 3

__global__ __launch_bounds__(128, 3) void attn_mma_kernel(float* __restrict__ out)
{
    extern __shared__ char ds[];
    const int tid  = threadIdx.x;
    const int w    = tid >> 5;
    const int lane = tid & 31;
    const int gid  = lane >> 2;
    const int tig  = lane & 3;
    const int bh   = blockIdx.y;
    const int q0   = blockIdx.x * 64;

    const size_t base = (size_t)bh * SEQ * HD;
    const uint32_t smb = smem_u32(ds);

    // Q fragments (fp16, pre-scaled), registers for the whole kernel
    uint32_t qh[4][4];
    {
        const __half* Q = g_Q16 + base;
        const int r0 = q0 + w * 16 + gid;
        #pragma unroll
        for (int kt = 0; kt < 4; kt++) {
            const int c0 = kt * 16 + 2 * tig;
            qh[kt][0] = *(const uint32_t*)(Q + (size_t)r0 * HD + c0);
            qh[kt][1] = *(const uint32_t*)(Q + (size_t)(r0 + 8) * HD + c0);
            qh[kt][2] = *(const uint32_t*)(Q + (size_t)r0 * HD + c0 + 8);
            qh[kt][3] = *(const uint32_t*)(Q + (size_t)(r0 + 8) * HD + c0 + 8);
        }
    }

    const __half* tsrc[2] = { g_K16 + base, g_V16 + base };

    auto issue = [&](int c) {
        const uint32_t sb = smb + (c % NSTAGE) * ASTAGE;
        const int k0 = c * 64;
        #pragma unroll
        for (int i = 0; i < 8; i++) {
            const int ch = tid + i * 128;                 // 1024 chunks total
            const int t2 = ch >> 9, row = (ch >> 3) & 63, seg = (ch & 7) * 16;
            CP_ASYNC16(sb + t2 * ATILE + row * 144 + seg,
                       (const void*)((const char*)(tsrc[t2] + (size_t)(k0 + row) * HD) + seg));
        }
        CP_COMMIT();
    };

    float m_r[2] = { -1e30f, -1e30f };
    float l_r[2] = { 0.f, 0.f };
    float oacc[8][4];
    #pragma unroll
    for (int j = 0; j < 8; j++)
        #pragma unroll
        for (int e = 0; e < 4; e++) oacc[j][e] = 0.f;

    const int b_row = lane & 7;
    const int b_kb  = ((lane >> 3) & 1) * 16;
    const int b_nx  = (lane & 16) ? 8 : 0;
    const int v_row = lane & 15;
    const int v_cb  = (lane & 16) ? 16 : 0;

    issue(0);
    issue(1);

    for (int c = 0; c < 32; c++) {
        if (c + 1 < 32) { CP_WAIT(1); } else { CP_WAIT(0); }
        __syncthreads();                 // orders prior-iter reads before overwrite below
        if (c + 2 < 32) issue(c + 2);

        const uint32_t Kb = smb + (c % NSTAGE) * ASTAGE;
        const uint32_t Vb = Kb + ATILE;

        // ---- S = Q K^T (1 pass) ----
        float sacc[8][4];
        #pragma unroll
        for (int j = 0; j < 8; j++)
            #pragma unroll
            for (int e = 0; e < 4; e++) sacc[j][e] = 0.f;

        #pragma unroll
        for (int kt = 0; kt < 4; kt++) {
            const int kb = kt * 32;
            uint32_t bK[4][4];
            #pragma unroll
            for (int p = 0; p < 4; p++)
                ldsm_x4(bK[p], Kb + (p * 16 + b_nx + b_row) * 144 + kb + b_kb);
            #pragma unroll
            for (int j = 0; j < 8; j++)
                mma16816h(sacc[j], qh[kt], &bK[j >> 1][(j & 1) * 2]);
        }

        // ---- online softmax ----
        float mx0 = -1e30f, mx1 = -1e30f;
        #pragma unroll
        for (int j = 0; j < 8; j++) {
            mx0 = fmaxf(mx0, fmaxf(sacc[j][0], sacc[j][1]));
            mx1 = fmaxf(mx1, fmaxf(sacc[j][2], sacc[j][3]));
        }
        mx0 = fmaxf(mx0, __shfl_xor_sync(0xffffffffu, mx0, 1));
        mx0 = fmaxf(mx0, __shfl_xor_sync(0xffffffffu, mx0, 2));
        mx1 = fmaxf(mx1, __shfl_xor_sync(0xffffffffu, mx1, 1));
        mx1 = fmaxf(mx1, __shfl_xor_sync(0xffffffffu, mx1, 2));

        const float mn0 = fmaxf(m_r[0], mx0);
        const float mn1 = fmaxf(m_r[1], mx1);
        const float al0 = __expf(m_r[0] - mn0);
        const float al1 = __expf(m_r[1] - mn1);
        m_r[0] = mn0; m_r[1] = mn1;

        uint32_t pa[4][4];
        float rs0 = 0.f, rs1 = 0.f;
        #pragma unroll
        for (int j = 0; j < 8; j++) {
            float p0 = __expf(sacc[j][0] - mn0);
            float p1 = __expf(sacc[j][1] - mn0);
            float p2 = __expf(sacc[j][2] - mn1);
            float p3 = __expf(sacc[j][3] - mn1);
            rs0 += p0 + p1; rs1 += p2 + p3;
            const int kt2 = j >> 1, rb = (j & 1) * 2;
            pa[kt2][rb + 0] = pack_h2(p0, p1);
            pa[kt2][rb + 1] = pack_h2(p2, p3);
        }
        rs0 += __shfl_xor_sync(0xffffffffu, rs0, 1);
        rs0 += __shfl_xor_sync(0xffffffffu, rs0, 2);
        rs1 += __shfl_xor_sync(0xffffffffu, rs1, 1);
        rs1 += __shfl_xor_sync(0xffffffffu, rs1, 2);
        l_r[0] = l_r[0] * al0 + rs0;
        l_r[1] = l_r[1] * al1 + rs1;

        #pragma unroll
        for (int j = 0; j < 8; j++) {
            oacc[j][0] *= al0; oacc[j][1] *= al0;
            oacc[j][2] *= al1; oacc[j][3] *= al1;
        }

        // ---- O += P V (1 pass) ----
        #pragma unroll
        for (int kt2 = 0; kt2 < 4; kt2++) {
            uint32_t bV[4][4];
            #pragma unroll
            for (int p = 0; p < 4; p++)
                ldsm_x4_t(bV[p], Vb + (kt2 * 16 + v_row) * 144 + p * 32 + v_cb);
            #pragma unroll
            for (int j = 0; j < 8; j++)
                mma16816h(oacc[j], pa[kt2], &bV[j >> 1][(j & 1) * 2]);
        }
    }

    // ---- epilogue ----
    const int bb = bh >> 4;
    const int h  = bh & 15;
    const float inv0 = 1.f / l_r[0];
    const float inv1 = 1.f / l_r[1];
    const int qr = q0 + w * 16 + gid;
    #pragma unroll
    for (int j = 0; j < 8; j++) {
        const int dd = 8 * j + 2 * tig;
        float2 v0 = make_float2(oacc[j][0] * inv0, oacc[j][1] * inv0);
        float2 v1 = make_float2(oacc[j][2] * inv1, oacc[j][3] * inv1);
        *(float2*)&out[((size_t)(bb * SEQ + qr)) * EMS + h * HD + dd]     = v0;
        *(float2*)&out[((size_t)(bb * SEQ + qr + 8)) * EMS + h * HD + dd] = v1;
    }
}

// ---------------------------------------------------------------------------
extern "C" void kernel_launch(void* const* d_in, const int* in_sizes, int n_in,
                              void* d_out, int out_size)
{
    const float* embed = (const float*)d_in[0];
    const float* q     = (const float*)d_in[1];
    const float* Wk    = (const float*)d_in[2];
    const float* bk    = (const float*)d_in[3];
    const float* Wq    = (const float*)d_in[4];
    const float* bq    = (const float*)d_in[5];
    const float* Wv    = (const float*)d_in[6];
    const float* bv    = (const float*)d_in[7];
    float* out = (float*)d_out;

    convert_kernel<<<dim3(4096, 5), 256>>>(embed, q, Wq, Wk, Wv);

    cudaFuncSetAttribute(proj_mma_kernel, cudaFuncAttributeMaxDynamicSharedMemorySize, PSTAGE * BUF_B);
    proj_mma_kernel<<<dim3(EMS / 128, (BATCH * SEQ) / 128, 3), 256, PSTAGE * BUF_B>>>(bq, bk, bv);

    cudaFuncSetAttribute(attn_mma_kernel, cudaFuncAttributeMaxDynamicSharedMemorySize, NSTAGE * ASTAGE);
    attn_mma_kernel<<<dim3(SEQ / 64, BATCH * NH), 128, NSTAGE * ASTAGE>>>(out);
}

// round 11
// speedup vs baseline: 8.0029x; 1.0814x over previous
#include <cuda_runtime.h>
#include <cuda_fp16.h>
#include <cstdint>

#define EMS 1024
#define NH 16
#define HD 64
#define SEQ 2048
#define BATCH 2

// ---------------------------------------------------------------------------
// PTX helpers
// ---------------------------------------------------------------------------
__device__ __forceinline__ uint32_t smem_u32(const void* p) {
    uint32_t a;
    asm("{ .reg .u64 t; cvta.to.shared.u64 t, %1; cvt.u32.u64 %0, t; }" : "=r"(a) : "l"(p));
    return a;
}
#define CP_ASYNC16(dst, src) \
    asm volatile("cp.async.cg.shared.global [%0], [%1], 16;" :: "r"(dst), "l"(src) : "memory")
#define CP_COMMIT() asm volatile("cp.async.commit_group;" ::: "memory")
#define CP_WAIT(n)  asm volatile("cp.async.wait_group %0;" :: "n"(n) : "memory")

__device__ __forceinline__ void ldsm_x4(uint32_t* r, uint32_t addr) {
    asm volatile("ldmatrix.sync.aligned.m8n8.x4.shared.b16 {%0,%1,%2,%3}, [%4];"
        : "=r"(r[0]), "=r"(r[1]), "=r"(r[2]), "=r"(r[3]) : "r"(addr));
}
__device__ __forceinline__ void ldsm_x4_t(uint32_t* r, uint32_t addr) {
    asm volatile("ldmatrix.sync.aligned.m8n8.x4.trans.shared.b16 {%0,%1,%2,%3}, [%4];"
        : "=r"(r[0]), "=r"(r[1]), "=r"(r[2]), "=r"(r[3]) : "r"(addr));
}
__device__ __forceinline__ void mma16816h(float* c, const uint32_t* a, const uint32_t* b) {
    asm volatile("mma.sync.aligned.m16n8k16.row.col.f32.f16.f16.f32 "
        "{%0,%1,%2,%3}, {%4,%5,%6,%7}, {%8,%9}, {%0,%1,%2,%3};"
        : "+f"(c[0]), "+f"(c[1]), "+f"(c[2]), "+f"(c[3])
        : "r"(a[0]), "r"(a[1]), "r"(a[2]), "r"(a[3]), "r"(b[0]), "r"(b[1]));
}
__device__ __forceinline__ uint32_t pack_h2(float lo, float hi) {
    __half2 t = __floats2half2_rn(lo, hi);
    return *(uint32_t*)&t;
}

// ---------------------------------------------------------------------------
// Device scratch (fp16)
// ---------------------------------------------------------------------------
__device__ __half g_Q16[BATCH*NH*SEQ*HD];   // pre-scaled by 0.125*log2(e)
__device__ __half g_K16[BATCH*NH*SEQ*HD];
__device__ __half g_V16[BATCH*NH*SEQ*HD];
__device__ __half g_E16[4096 * 1024];
__device__ __half g_X16[4096 * 1024];
__device__ __half g_Wq16[1024 * 1024], g_Wk16[1024 * 1024], g_Wv16[1024 * 1024];

// ---------------------------------------------------------------------------
// fp32 -> fp16 convert, MLP=4 (4 independent float4 loads in flight)
// ---------------------------------------------------------------------------
__global__ __launch_bounds__(256) void convert_kernel(
    const float* __restrict__ embed, const float* __restrict__ qin,
    const float* __restrict__ Wq, const float* __restrict__ Wk, const float* __restrict__ Wv)
{
    const int z = blockIdx.y;
    const float* src; __half* dst; int n4;
    switch (z) {
        case 0: src = embed; dst = g_E16;  n4 = 4096 * 256; break;
        case 1: src = qin;   dst = g_X16;  n4 = 4096 * 256; break;
        case 2: src = Wq;    dst = g_Wq16; n4 = 1024 * 256; break;
        case 3: src = Wk;    dst = g_Wk16; n4 = 1024 * 256; break;
        default: src = Wv;   dst = g_Wv16; n4 = 1024 * 256; break;
    }
    const int base = blockIdx.x * 1024 + threadIdx.x;
    if (base >= n4) return;
    float4 v[4];
    #pragma unroll
    for (int i = 0; i < 4; i++) {
        const int t = base + i * 256;
        if (t < n4) v[i] = ((const float4*)src)[t];
    }
    #pragma unroll
    for (int i = 0; i < 4; i++) {
        const int t = base + i * 256;
        if (t < n4)
            *(uint2*)(dst + (size_t)t * 4) =
                make_uint2(pack_h2(v[i].x, v[i].y), pack_h2(v[i].z, v[i].w));
    }
}

// ---------------------------------------------------------------------------
// fp16 1-pass projection: C = A @ W^T + bias. 128x128 CTA tile, 8 warps 4x2.
// 3-stage cp.async pipeline; single sync per iteration.
// ---------------------------------------------------------------------------
#define TILE_B 18432            // 128 rows * 144 B
#define BUF_B  (2 * TILE_B)     // A, W
#define PSTAGE 3

__global__ __launch_bounds__(256, 2) void proj_mma_kernel(
    const float* __restrict__ bq, const float* __restrict__ bk, const float* __restrict__ bv)
{
    extern __shared__ char ds[];
    __shared__ float s_bias[128];

    const int tid  = threadIdx.x;
    const int wid  = tid >> 5;
    const int lane = tid & 31;
    const int z  = blockIdx.z;
    const int n0 = blockIdx.x * 128;
    const int m0 = blockIdx.y * 128;

    const __half *A, *W; const float* bias;
    if (z == 0)      { A = g_X16; W = g_Wq16; bias = bq; }
    else if (z == 1) { A = g_E16; W = g_Wk16; bias = bk; }
    else             { A = g_E16; W = g_Wv16; bias = bv; }

    if (tid < 128) s_bias[tid] = bias[n0 + tid];

    const uint32_t smb = smem_u32(ds);
    const __half* srcs[2] = { A + (size_t)m0 * 1024, W + (size_t)n0 * 1024 };

    const int cprow = tid >> 3;
    const int cpseg = (tid & 7) * 16;

    auto issue = [&](int c) {
        const uint32_t bbase = smb + (c % PSTAGE) * BUF_B;
        const int k0 = c * 64;
        #pragma unroll
        for (int t2 = 0; t2 < 2; t2++) {
            const __half* sp = srcs[t2] + k0;
            const uint32_t tbase = bbase + t2 * TILE_B;
            #pragma unroll
            for (int it = 0; it < 4; it++) {
                const int r = cprow + it * 32;
                CP_ASYNC16(tbase + r * 144 + cpseg,
                           (const void*)((const char*)(sp + (size_t)r * 1024) + cpseg));
            }
        }
        CP_COMMIT();
    };

    const int wm = (wid >> 1) * 32;
    const int wn = (wid & 1) * 64;

    float acc[2][8][4];
    #pragma unroll
    for (int mt = 0; mt < 2; mt++)
        #pragma unroll
        for (int nt = 0; nt < 8; nt++)
            #pragma unroll
            for (int e = 0; e < 4; e++) acc[mt][nt][e] = 0.f;

    const int a_row = lane & 15;
    const int a_kb  = ((lane >> 4) << 3) * 2;
    const int b_row = lane & 7;
    const int b_kb  = (((lane >> 3) & 1) << 3) * 2;
    const int b_nx  = (lane >= 16) ? 8 : 0;

    issue(0);
    issue(1);

    for (int c = 0; c < 16; c++) {
        if (c + 1 < 16) { CP_WAIT(1); } else { CP_WAIT(0); }
        __syncthreads();
        if (c + 2 < 16) issue(c + 2);

        const uint32_t bbase = smb + (c % PSTAGE) * BUF_B;
        const uint32_t Abase = bbase;
        const uint32_t Wbase = bbase + TILE_B;

        #pragma unroll
        for (int ks = 0; ks < 4; ks++) {
            const int kb = ks * 32;
            uint32_t aF[2][4];
            #pragma unroll
            for (int mt = 0; mt < 2; mt++)
                ldsm_x4(aF[mt], Abase + (wm + mt * 16 + a_row) * 144 + kb + a_kb);

            uint32_t bF[8][2];
            #pragma unroll
            for (int p = 0; p < 4; p++) {
                uint32_t r4[4];
                ldsm_x4(r4, Wbase + (wn + p * 16 + b_nx + b_row) * 144 + kb + b_kb);
                bF[2 * p][0] = r4[0];     bF[2 * p][1] = r4[1];
                bF[2 * p + 1][0] = r4[2]; bF[2 * p + 1][1] = r4[3];
            }

            #pragma unroll
            for (int mt = 0; mt < 2; mt++)
                #pragma unroll
                for (int nt = 0; nt < 8; nt++)
                    mma16816h(acc[mt][nt], aF[mt], bF[nt]);
        }
    }

    // Epilogue: bias, (Q) scale into exp2 domain, fp16 pack, [b,h,s,d]
    __half* dst = (z == 0) ? g_Q16 : (z == 1) ? g_K16 : g_V16;
    const float osc = (z == 0) ? 0.125f * 1.44269504f : 1.0f;
    const int rq = lane >> 2;
    const int cq = (lane & 3) * 2;
    #pragma unroll
    for (int mt = 0; mt < 2; mt++) {
        #pragma unroll
        for (int half = 0; half < 2; half++) {
            const int m  = m0 + wm + mt * 16 + rq + half * 8;
            const int bb = m >> 11;
            const int s  = m & (SEQ - 1);
            #pragma unroll
            for (int nt = 0; nt < 8; nt++) {
                const int nl = wn + nt * 8 + cq;
                const int n  = n0 + nl;
                const int h  = n >> 6, dd = n & 63;
                float vx = (acc[mt][nt][half * 2 + 0] + s_bias[nl])     * osc;
                float vy = (acc[mt][nt][half * 2 + 1] + s_bias[nl + 1]) * osc;
                const size_t idx = (((size_t)(bb * NH + h) * SEQ) + s) * HD + dd;
                *(uint32_t*)(dst + idx) = pack_h2(vx, vy);
            }
        }
    }
}

// ---------------------------------------------------------------------------
// Tensor-core flash attention, fp16, exp2-domain softmax.
// 4-warp CTAs, 16 q-rows/warp, OCCUPANCY 4 (16 warps/SM) -> fills softmax/
// ldsm gaps and cuts CTA-quantization (1024 CTAs / 592 slots = 1.73 waves).
// 64-key tiles, 3-stage cp.async, one sync per iteration.
// ---------------------------------------------------------------------------
#define ATILE 9216              // 64 rows * 144B
#define ASTAGE (2 * ATILE)      // K, V
#define NSTAGE 3

__global__ __launch_bounds__(128, 4) void attn_mma_kernel(float* __restrict__ out)
{
    extern __shared__ char ds[];
    const int tid  = threadIdx.x;
    const int w    = tid >> 5;
    const int lane = tid & 31;
    const int gid  = lane >> 2;
    const int tig  = lane & 3;
    const int bh   = blockIdx.y;
    const int q0   = blockIdx.x * 64;

    const size_t base = (size_t)bh * SEQ * HD;
    const uint32_t smb = smem_u32(ds);

    // Q fragments (fp16, pre-scaled into exp2 domain)
    uint32_t qh[4][4];
    {
        const __half* Q = g_Q16 + base;
        const int r0 = q0 + w * 16 + gid;
        #pragma unroll
        for (int kt = 0; kt < 4; kt++) {
            const int c0 = kt * 16 + 2 * tig;
            qh[kt][0] = *(const uint32_t*)(Q + (size_t)r0 * HD + c0);
            qh[kt][1] = *(const uint32_t*)(Q + (size_t)(r0 + 8) * HD + c0);
            qh[kt][2] = *(const uint32_t*)(Q + (size_t)r0 * HD + c0 + 8);
            qh[kt][3] = *(const uint32_t*)(Q + (size_t)(r0 + 8) * HD + c0 + 8);
        }
    }

    const __half* tsrc[2] = { g_K16 + base, g_V16 + base };

    auto issue = [&](int c) {
        const uint32_t sb = smb + (c % NSTAGE) * ASTAGE;
        const int k0 = c * 64;
        #pragma unroll
        for (int i = 0; i < 8; i++) {
            const int ch = tid + i * 128;
            const int t2 = ch >> 9, row = (ch >> 3) & 63, seg = (ch & 7) * 16;
            CP_ASYNC16(sb + t2 * ATILE + row * 144 + seg,
                       (const void*)((const char*)(tsrc[t2] + (size_t)(k0 + row) * HD) + seg));
        }
        CP_COMMIT();
    };

    float m_r[2] = { -1e30f, -1e30f };
    float l_r[2] = { 0.f, 0.f };
    float oacc[8][4];
    #pragma unroll
    for (int j = 0; j < 8; j++)
        #pragma unroll
        for (int e = 0; e < 4; e++) oacc[j][e] = 0.f;

    const int b_row = lane & 7;
    const int b_kb  = ((lane >> 3) & 1) * 16;
    const int b_nx  = (lane & 16) ? 8 : 0;
    const int v_row = lane & 15;
    const int v_cb  = (lane & 16) ? 16 : 0;

    issue(0);
    issue(1);

    for (int c = 0; c < 32; c++) {
        if (c + 1 < 32) { CP_WAIT(1); } else { CP_WAIT(0); }
        __syncthreads();
        if (c + 2 < 32) issue(c + 2);

        const uint32_t Kb = smb + (c % NSTAGE) * ASTAGE;
        const uint32_t Vb = Kb + ATILE;

        // ---- S = Q K^T (1 pass, exp2 domain) ----
        float sacc[8][4];
        #pragma unroll
        for (int j = 0; j < 8; j++)
            #pragma unroll
            for (int e = 0; e < 4; e++) sacc[j][e] = 0.f;

        #pragma unroll
        for (int kt = 0; kt < 4; kt++) {
            const int kb = kt * 32;
            uint32_t bK[4][4];
            #pragma unroll
            for (int p = 0; p < 4; p++)
                ldsm_x4(bK[p], Kb + (p * 16 + b_nx + b_row) * 144 + kb + b_kb);
            #pragma unroll
            for (int j = 0; j < 8; j++)
                mma16816h(sacc[j], qh[kt], &bK[j >> 1][(j & 1) * 2]);
        }

        // ---- online softmax (exp2) ----
        float mx0 = -1e30f, mx1 = -1e30f;
        #pragma unroll
        for (int j = 0; j < 8; j++) {
            mx0 = fmaxf(mx0, fmaxf(sacc[j][0], sacc[j][1]));
            mx1 = fmaxf(mx1, fmaxf(sacc[j][2], sacc[j][3]));
        }
        mx0 = fmaxf(mx0, __shfl_xor_sync(0xffffffffu, mx0, 1));
        mx0 = fmaxf(mx0, __shfl_xor_sync(0xffffffffu, mx0, 2));
        mx1 = fmaxf(mx1, __shfl_xor_sync(0xffffffffu, mx1, 1));
        mx1 = fmaxf(mx1, __shfl_xor_sync(0xffffffffu, mx1, 2));

        const float mn0 = fmaxf(m_r[0], mx0);
        const float mn1 = fmaxf(m_r[1], mx1);
        const float al0 = exp2f(m_r[0] - mn0);
        const float al1 = exp2f(m_r[1] - mn1);
        m_r[0] = mn0; m_r[1] = mn1;

        uint32_t pa[4][4];
        float rs0 = 0.f, rs1 = 0.f;
        #pragma unroll
        for (int j = 0; j < 8; j++) {
            float p0 = exp2f(sacc[j][0] - mn0);
            float p1 = exp2f(sacc[j][1] - mn0);
            float p2 = exp2f(sacc[j][2] - mn1);
            float p3 = exp2f(sacc[j][3] - mn1);
            rs0 += p0 + p1; rs1 += p2 + p3;
            const int kt2 = j >> 1, rb = (j & 1) * 2;
            pa[kt2][rb + 0] = pack_h2(p0, p1);
            pa[kt2][rb + 1] = pack_h2(p2, p3);
        }
        rs0 += __shfl_xor_sync(0xffffffffu, rs0, 1);
        rs0 += __shfl_xor_sync(0xffffffffu, rs0, 2);
        rs1 += __shfl_xor_sync(0xffffffffu, rs1, 1);
        rs1 += __shfl_xor_sync(0xffffffffu, rs1, 2);
        l_r[0] = l_r[0] * al0 + rs0;
        l_r[1] = l_r[1] * al1 + rs1;

        #pragma unroll
        for (int j = 0; j < 8; j++) {
            oacc[j][0] *= al0; oacc[j][1] *= al0;
            oacc[j][2] *= al1; oacc[j][3] *= al1;
        }

        // ---- O += P V (1 pass) ----
        #pragma unroll
        for (int kt2 = 0; kt2 < 4; kt2++) {
            uint32_t bV[4][4];
            #pragma unroll
            for (int p = 0; p < 4; p++)
                ldsm_x4_t(bV[p], Vb + (kt2 * 16 + v_row) * 144 + p * 32 + v_cb);
            #pragma unroll
            for (int j = 0; j < 8; j++)
                mma16816h(oacc[j], pa[kt2], &bV[j >> 1][(j & 1) * 2]);
        }
    }

    // ---- epilogue ----
    const int bb = bh >> 4;
    const int h  = bh & 15;
    const float inv0 = 1.f / l_r[0];
    const float inv1 = 1.f / l_r[1];
    const int qr = q0 + w * 16 + gid;
    #pragma unroll
    for (int j = 0; j < 8; j++) {
        const int dd = 8 * j + 2 * tig;
        float2 v0 = make_float2(oacc[j][0] * inv0, oacc[j][1] * inv0);
        float2 v1 = make_float2(oacc[j][2] * inv1, oacc[j][3] * inv1);
        *(float2*)&out[((size_t)(bb * SEQ + qr)) * EMS + h * HD + dd]     = v0;
        *(float2*)&out[((size_t)(bb * SEQ + qr + 8)) * EMS + h * HD + dd] = v1;
    }
}

// ---------------------------------------------------------------------------
extern "C" void kernel_launch(void* const* d_in, const int* in_sizes, int n_in,
                              void* d_out, int out_size)
{
    const float* embed = (const float*)d_in[0];
    const float* q     = (const float*)d_in[1];
    const float* Wk    = (const float*)d_in[2];
    const float* bk    = (const float*)d_in[3];
    const float* Wq    = (const float*)d_in[4];
    const float* bq    = (const float*)d_in[5];
    const float* Wv    = (const float*)d_in[6];
    const float* bv    = (const float*)d_in[7];
    float* out = (float*)d_out;

    convert_kernel<<<dim3(1024, 5), 256>>>(embed, q, Wq, Wk, Wv);

    cudaFuncSetAttribute(proj_mma_kernel, cudaFuncAttributeMaxDynamicSharedMemorySize, PSTAGE * BUF_B);
    proj_mma_kernel<<<dim3(EMS / 128, (BATCH * SEQ) / 128, 3), 256, PSTAGE * BUF_B>>>(bq, bk, bv);

    cudaFuncSetAttribute(attn_mma_kernel, cudaFuncAttributeMaxDynamicSharedMemorySize, NSTAGE * ASTAGE);
    attn_mma_kernel<<<dim3(SEQ / 64, BATCH * NH), 128, NSTAGE * ASTAGE>>>(out);
}

// round 12
// speedup vs baseline: 8.0199x; 1.0021x over previous
#include <cuda_runtime.h>
#include <cuda_fp16.h>
#include <cstdint>

#define EMS 1024
#define NH 16
#define HD 64
#define SEQ 2048
#define BATCH 2

// ---------------------------------------------------------------------------
// PTX helpers
// ---------------------------------------------------------------------------
__device__ __forceinline__ uint32_t smem_u32(const void* p) {
    uint32_t a;
    asm("{ .reg .u64 t; cvta.to.shared.u64 t, %1; cvt.u32.u64 %0, t; }" : "=r"(a) : "l"(p));
    return a;
}
#define CP_ASYNC16(dst, src) \
    asm volatile("cp.async.cg.shared.global [%0], [%1], 16;" :: "r"(dst), "l"(src) : "memory")
#define CP_COMMIT() asm volatile("cp.async.commit_group;" ::: "memory")
#define CP_WAIT(n)  asm volatile("cp.async.wait_group %0;" :: "n"(n) : "memory")

__device__ __forceinline__ void ldsm_x4(uint32_t* r, uint32_t addr) {
    asm volatile("ldmatrix.sync.aligned.m8n8.x4.shared.b16 {%0,%1,%2,%3}, [%4];"
        : "=r"(r[0]), "=r"(r[1]), "=r"(r[2]), "=r"(r[3]) : "r"(addr));
}
__device__ __forceinline__ void ldsm_x4_t(uint32_t* r, uint32_t addr) {
    asm volatile("ldmatrix.sync.aligned.m8n8.x4.trans.shared.b16 {%0,%1,%2,%3}, [%4];"
        : "=r"(r[0]), "=r"(r[1]), "=r"(r[2]), "=r"(r[3]) : "r"(addr));
}
__device__ __forceinline__ void mma16816h(float* c, const uint32_t* a, const uint32_t* b) {
    asm volatile("mma.sync.aligned.m16n8k16.row.col.f32.f16.f16.f32 "
        "{%0,%1,%2,%3}, {%4,%5,%6,%7}, {%8,%9}, {%0,%1,%2,%3};"
        : "+f"(c[0]), "+f"(c[1]), "+f"(c[2]), "+f"(c[3])
        : "r"(a[0]), "r"(a[1]), "r"(a[2]), "r"(a[3]), "r"(b[0]), "r"(b[1]));
}
__device__ __forceinline__ uint32_t pack_h2(float lo, float hi) {
    __half2 t = __floats2half2_rn(lo, hi);
    return *(uint32_t*)&t;
}
// one MUFU op -> two fp16 exp2 results, already packed for the PV A-fragment
__device__ __forceinline__ uint32_t h2exp2(uint32_t a) {
    uint32_t r;
    asm("ex2.approx.f16x2 %0, %1;" : "=r"(r) : "r"(a));
    return r;
}

// ---------------------------------------------------------------------------
// Device scratch (fp16)
// ---------------------------------------------------------------------------
__device__ __half g_Q16[BATCH*NH*SEQ*HD];   // pre-scaled by 0.125*log2(e)
__device__ __half g_K16[BATCH*NH*SEQ*HD];
__device__ __half g_V16[BATCH*NH*SEQ*HD];
__device__ __half g_E16[4096 * 1024];
__device__ __half g_X16[4096 * 1024];
__device__ __half g_Wq16[1024 * 1024], g_Wk16[1024 * 1024], g_Wv16[1024 * 1024];

// ---------------------------------------------------------------------------
// fp32 -> fp16 convert, MLP=4
// ---------------------------------------------------------------------------
__global__ __launch_bounds__(256) void convert_kernel(
    const float* __restrict__ embed, const float* __restrict__ qin,
    const float* __restrict__ Wq, const float* __restrict__ Wk, const float* __restrict__ Wv)
{
    const int z = blockIdx.y;
    const float* src; __half* dst; int n4;
    switch (z) {
        case 0: src = embed; dst = g_E16;  n4 = 4096 * 256; break;
        case 1: src = qin;   dst = g_X16;  n4 = 4096 * 256; break;
        case 2: src = Wq;    dst = g_Wq16; n4 = 1024 * 256; break;
        case 3: src = Wk;    dst = g_Wk16; n4 = 1024 * 256; break;
        default: src = Wv;   dst = g_Wv16; n4 = 1024 * 256; break;
    }
    const int base = blockIdx.x * 1024 + threadIdx.x;
    if (base >= n4) return;
    float4 v[4];
    #pragma unroll
    for (int i = 0; i < 4; i++) {
        const int t = base + i * 256;
        if (t < n4) v[i] = ((const float4*)src)[t];
    }
    #pragma unroll
    for (int i = 0; i < 4; i++) {
        const int t = base + i * 256;
        if (t < n4)
            *(uint2*)(dst + (size_t)t * 4) =
                make_uint2(pack_h2(v[i].x, v[i].y), pack_h2(v[i].z, v[i].w));
    }
}

// ---------------------------------------------------------------------------
// fp16 1-pass projection: C = A @ W^T + bias. 128x128 CTA tile, 8 warps 4x2.
// 3-stage cp.async pipeline.
// ---------------------------------------------------------------------------
#define TILE_B 18432            // 128 rows * 144 B
#define BUF_B  (2 * TILE_B)     // A, W
#define PSTAGE 3

__global__ __launch_bounds__(256, 2) void proj_mma_kernel(
    const float* __restrict__ bq, const float* __restrict__ bk, const float* __restrict__ bv)
{
    extern __shared__ char ds[];
    __shared__ float s_bias[128];

    const int tid  = threadIdx.x;
    const int wid  = tid >> 5;
    const int lane = tid & 31;
    const int z  = blockIdx.z;
    const int n0 = blockIdx.x * 128;
    const int m0 = blockIdx.y * 128;

    const __half *A, *W; const float* bias;
    if (z == 0)      { A = g_X16; W = g_Wq16; bias = bq; }
    else if (z == 1) { A = g_E16; W = g_Wk16; bias = bk; }
    else             { A = g_E16; W = g_Wv16; bias = bv; }

    if (tid < 128) s_bias[tid] = bias[n0 + tid];

    const uint32_t smb = smem_u32(ds);
    const __half* srcs[2] = { A + (size_t)m0 * 1024, W + (size_t)n0 * 1024 };

    const int cprow = tid >> 3;
    const int cpseg = (tid & 7) * 16;

    auto issue = [&](int c) {
        const uint32_t bbase = smb + (c % PSTAGE) * BUF_B;
        const int k0 = c * 64;
        #pragma unroll
        for (int t2 = 0; t2 < 2; t2++) {
            const __half* sp = srcs[t2] + k0;
            const uint32_t tbase = bbase + t2 * TILE_B;
            #pragma unroll
            for (int it = 0; it < 4; it++) {
                const int r = cprow + it * 32;
                CP_ASYNC16(tbase + r * 144 + cpseg,
                           (const void*)((const char*)(sp + (size_t)r * 1024) + cpseg));
            }
        }
        CP_COMMIT();
    };

    const int wm = (wid >> 1) * 32;
    const int wn = (wid & 1) * 64;

    float acc[2][8][4];
    #pragma unroll
    for (int mt = 0; mt < 2; mt++)
        #pragma unroll
        for (int nt = 0; nt < 8; nt++)
            #pragma unroll
            for (int e = 0; e < 4; e++) acc[mt][nt][e] = 0.f;

    const int a_row = lane & 15;
    const int a_kb  = ((lane >> 4) << 3) * 2;
    const int b_row = lane & 7;
    const int b_kb  = (((lane >> 3) & 1) << 3) * 2;
    const int b_nx  = (lane >= 16) ? 8 : 0;

    issue(0);
    issue(1);

    for (int c = 0; c < 16; c++) {
        if (c + 1 < 16) { CP_WAIT(1); } else { CP_WAIT(0); }
        __syncthreads();
        if (c + 2 < 16) issue(c + 2);

        const uint32_t bbase = smb + (c % PSTAGE) * BUF_B;
        const uint32_t Abase = bbase;
        const uint32_t Wbase = bbase + TILE_B;

        #pragma unroll
        for (int ks = 0; ks < 4; ks++) {
            const int kb = ks * 32;
            uint32_t aF[2][4];
            #pragma unroll
            for (int mt = 0; mt < 2; mt++)
                ldsm_x4(aF[mt], Abase + (wm + mt * 16 + a_row) * 144 + kb + a_kb);

            uint32_t bF[8][2];
            #pragma unroll
            for (int p = 0; p < 4; p++) {
                uint32_t r4[4];
                ldsm_x4(r4, Wbase + (wn + p * 16 + b_nx + b_row) * 144 + kb + b_kb);
                bF[2 * p][0] = r4[0];     bF[2 * p][1] = r4[1];
                bF[2 * p + 1][0] = r4[2]; bF[2 * p + 1][1] = r4[3];
            }

            #pragma unroll
            for (int mt = 0; mt < 2; mt++)
                #pragma unroll
                for (int nt = 0; nt < 8; nt++)
                    mma16816h(acc[mt][nt], aF[mt], bF[nt]);
        }
    }

    // Epilogue: bias, (Q) scale into exp2 domain, fp16 pack, [b,h,s,d]
    __half* dst = (z == 0) ? g_Q16 : (z == 1) ? g_K16 : g_V16;
    const float osc = (z == 0) ? 0.125f * 1.44269504f : 1.0f;
    const int rq = lane >> 2;
    const int cq = (lane & 3) * 2;
    #pragma unroll
    for (int mt = 0; mt < 2; mt++) {
        #pragma unroll
        for (int half = 0; half < 2; half++) {
            const int m  = m0 + wm + mt * 16 + rq + half * 8;
            const int bb = m >> 11;
            const int s  = m & (SEQ - 1);
            #pragma unroll
            for (int nt = 0; nt < 8; nt++) {
                const int nl = wn + nt * 8 + cq;
                const int n  = n0 + nl;
                const int h  = n >> 6, dd = n & 63;
                float vx = (acc[mt][nt][half * 2 + 0] + s_bias[nl])     * osc;
                float vy = (acc[mt][nt][half * 2 + 1] + s_bias[nl + 1]) * osc;
                const size_t idx = (((size_t)(bb * NH + h) * SEQ) + s) * HD + dd;
                *(uint32_t*)(dst + idx) = pack_h2(vx, vy);
            }
        }
    }
}

// ---------------------------------------------------------------------------
// Tensor-core flash attention, fp16, exp2-domain softmax with f16x2 MUFU.
// 4-warp CTAs, 16 q-rows/warp, occupancy 4. 64-key tiles, 3-stage cp.async.
// l is summed from the SAME fp16-rounded p used in PV (consistency).
// ---------------------------------------------------------------------------
#define ATILE 9216              // 64 rows * 144B
#define ASTAGE (2 * ATILE)      // K, V
#define NSTAGE 3

__global__ __launch_bounds__(128, 4) void attn_mma_kernel(float* __restrict__ out)
{
    extern __shared__ char ds[];
    const int tid  = threadIdx.x;
    const int w    = tid >> 5;
    const int lane = tid & 31;
    const int gid  = lane >> 2;
    const int tig  = lane & 3;
    const int bh   = blockIdx.y;
    const int q0   = blockIdx.x * 64;

    const size_t base = (size_t)bh * SEQ * HD;
    const uint32_t smb = smem_u32(ds);

    // Q fragments (fp16, pre-scaled into exp2 domain)
    uint32_t qh[4][4];
    {
        const __half* Q = g_Q16 + base;
        const int r0 = q0 + w * 16 + gid;
        #pragma unroll
        for (int kt = 0; kt < 4; kt++) {
            const int c0 = kt * 16 + 2 * tig;
            qh[kt][0] = *(const uint32_t*)(Q + (size_t)r0 * HD + c0);
            qh[kt][1] = *(const uint32_t*)(Q + (size_t)(r0 + 8) * HD + c0);
            qh[kt][2] = *(const uint32_t*)(Q + (size_t)r0 * HD + c0 + 8);
            qh[kt][3] = *(const uint32_t*)(Q + (size_t)(r0 + 8) * HD + c0 + 8);
        }
    }

    const __half* tsrc[2] = { g_K16 + base, g_V16 + base };

    auto issue = [&](int c) {
        const uint32_t sb = smb + (c % NSTAGE) * ASTAGE;
        const int k0 = c * 64;
        #pragma unroll
        for (int i = 0; i < 8; i++) {
            const int ch = tid + i * 128;
            const int t2 = ch >> 9, row = (ch >> 3) & 63, seg = (ch & 7) * 16;
            CP_ASYNC16(sb + t2 * ATILE + row * 144 + seg,
                       (const void*)((const char*)(tsrc[t2] + (size_t)(k0 + row) * HD) + seg));
        }
        CP_COMMIT();
    };

    float m_r[2] = { -1e30f, -1e30f };
    float l_r[2] = { 0.f, 0.f };
    float oacc[8][4];
    #pragma unroll
    for (int j = 0; j < 8; j++)
        #pragma unroll
        for (int e = 0; e < 4; e++) oacc[j][e] = 0.f;

    const int b_row = lane & 7;
    const int b_kb  = ((lane >> 3) & 1) * 16;
    const int b_nx  = (lane & 16) ? 8 : 0;
    const int v_row = lane & 15;
    const int v_cb  = (lane & 16) ? 16 : 0;

    issue(0);
    issue(1);

    for (int c = 0; c < 32; c++) {
        if (c + 1 < 32) { CP_WAIT(1); } else { CP_WAIT(0); }
        __syncthreads();
        if (c + 2 < 32) issue(c + 2);

        const uint32_t Kb = smb + (c % NSTAGE) * ASTAGE;
        const uint32_t Vb = Kb + ATILE;

        // ---- S = Q K^T (1 pass, exp2 domain) ----
        float sacc[8][4];
        #pragma unroll
        for (int j = 0; j < 8; j++)
            #pragma unroll
            for (int e = 0; e < 4; e++) sacc[j][e] = 0.f;

        #pragma unroll
        for (int kt = 0; kt < 4; kt++) {
            const int kb = kt * 32;
            uint32_t bK[4][4];
            #pragma unroll
            for (int p = 0; p < 4; p++)
                ldsm_x4(bK[p], Kb + (p * 16 + b_nx + b_row) * 144 + kb + b_kb);
            #pragma unroll
            for (int j = 0; j < 8; j++)
                mma16816h(sacc[j], qh[kt], &bK[j >> 1][(j & 1) * 2]);
        }

        // ---- online softmax (f16x2 ex2: 1 MUFU op per 2 p-values) ----
        float mx0 = -1e30f, mx1 = -1e30f;
        #pragma unroll
        for (int j = 0; j < 8; j++) {
            mx0 = fmaxf(mx0, fmaxf(sacc[j][0], sacc[j][1]));
            mx1 = fmaxf(mx1, fmaxf(sacc[j][2], sacc[j][3]));
        }
        mx0 = fmaxf(mx0, __shfl_xor_sync(0xffffffffu, mx0, 1));
        mx0 = fmaxf(mx0, __shfl_xor_sync(0xffffffffu, mx0, 2));
        mx1 = fmaxf(mx1, __shfl_xor_sync(0xffffffffu, mx1, 1));
        mx1 = fmaxf(mx1, __shfl_xor_sync(0xffffffffu, mx1, 2));

        const float mn0 = fmaxf(m_r[0], mx0);
        const float mn1 = fmaxf(m_r[1], mx1);
        const float al0 = exp2f(m_r[0] - mn0);
        const float al1 = exp2f(m_r[1] - mn1);
        m_r[0] = mn0; m_r[1] = mn1;

        uint32_t pa[4][4];
        float rs0 = 0.f, rs1 = 0.f;
        #pragma unroll
        for (int j = 0; j < 8; j++) {
            const uint32_t p01 = h2exp2(pack_h2(sacc[j][0] - mn0, sacc[j][1] - mn0));
            const uint32_t p23 = h2exp2(pack_h2(sacc[j][2] - mn1, sacc[j][3] - mn1));
            const int kt2 = j >> 1, rb = (j & 1) * 2;
            pa[kt2][rb + 0] = p01;
            pa[kt2][rb + 1] = p23;
            // l summed from the SAME rounded p used in PV
            float2 f01 = __half22float2(*(const __half2*)&p01);
            float2 f23 = __half22float2(*(const __half2*)&p23);
            rs0 += f01.x + f01.y;
            rs1 += f23.x + f23.y;
        }
        rs0 += __shfl_xor_sync(0xffffffffu, rs0, 1);
        rs0 += __shfl_xor_sync(0xffffffffu, rs0, 2);
        rs1 += __shfl_xor_sync(0xffffffffu, rs1, 1);
        rs1 += __shfl_xor_sync(0xffffffffu, rs1, 2);
        l_r[0] = l_r[0] * al0 + rs0;
        l_r[1] = l_r[1] * al1 + rs1;

        #pragma unroll
        for (int j = 0; j < 8; j++) {
            oacc[j][0] *= al0; oacc[j][1] *= al0;
            oacc[j][2] *= al1; oacc[j][3] *= al1;
        }

        // ---- O += P V (1 pass) ----
        #pragma unroll
        for (int kt2 = 0; kt2 < 4; kt2++) {
            uint32_t bV[4][4];
            #pragma unroll
            for (int p = 0; p < 4; p++)
                ldsm_x4_t(bV[p], Vb + (kt2 * 16 + v_row) * 144 + p * 32 + v_cb);
            #pragma unroll
            for (int j = 0; j < 8; j++)
                mma16816h(oacc[j], pa[kt2], &bV[j >> 1][(j & 1) * 2]);
        }
    }

    // ---- epilogue ----
    const int bb = bh >> 4;
    const int h  = bh & 15;
    const float inv0 = 1.f / l_r[0];
    const float inv1 = 1.f / l_r[1];
    const int qr = q0 + w * 16 + gid;
    #pragma unroll
    for (int j = 0; j < 8; j++) {
        const int dd = 8 * j + 2 * tig;
        float2 v0 = make_float2(oacc[j][0] * inv0, oacc[j][1] * inv0);
        float2 v1 = make_float2(oacc[j][2] * inv1, oacc[j][3] * inv1);
        *(float2*)&out[((size_t)(bb * SEQ + qr)) * EMS + h * HD + dd]     = v0;
        *(float2*)&out[((size_t)(bb * SEQ + qr + 8)) * EMS + h * HD + dd] = v1;
    }
}

// ---------------------------------------------------------------------------
extern "C" void kernel_launch(void* const* d_in, const int* in_sizes, int n_in,
                              void* d_out, int out_size)
{
    const float* embed = (const float*)d_in[0];
    const float* q     = (const float*)d_in[1];
    const float* Wk    = (const float*)d_in[2];
    const float* bk    = (const float*)d_in[3];
    const float* Wq    = (const float*)d_in[4];
    const float* bq    = (const float*)d_in[5];
    const float* Wv    = (const float*)d_in[6];
    const float* bv    = (const float*)d_in[7];
    float* out = (float*)d_out;

    convert_kernel<<<dim3(1024, 5), 256>>>(embed, q, Wq, Wk, Wv);

    cudaFuncSetAttribute(proj_mma_kernel, cudaFuncAttributeMaxDynamicSharedMemorySize, PSTAGE * BUF_B);
    proj_mma_kernel<<<dim3(EMS / 128, (BATCH * SEQ) / 128, 3), 256, PSTAGE * BUF_B>>>(bq, bk, bv);

    cudaFuncSetAttribute(attn_mma_kernel, cudaFuncAttributeMaxDynamicSharedMemorySize, NSTAGE * ASTAGE);
    attn_mma_kernel<<<dim3(SEQ / 64, BATCH * NH), 128, NSTAGE * ASTAGE>>>(out);
}